// round 12
// baseline (speedup 1.0000x reference)
#include <cuda_runtime.h>
#include <cuda_bf16.h>
#include <cuda_fp16.h>
#include <math.h>

#define NN 50000
#define NP 50048          // padded to 128
#define EE 800000
#define ET (EE + NN)      // edges + self loops
#define PIT 264           // smem row pitch (fp16): 33*16B -> LDSM conflict-free

// ---------------- scratch (device globals; no allocation allowed) ----------------
__device__ float d_T2[512 * 16];             // Hd @ Wr
__device__ float d_M[128 * 16];              // Wd @ T2
__device__ int   d_deg[NN];                  // starts 0; scan resets to 0 after use
__device__ int   d_rowoff[NN + 1];
__device__ int   d_cursor[NN];               // gcn_agg resets to 0 after scatter
__device__ float d_dis[NN];
__device__ int   d_csr[ET];
__device__ float d_xw[NN * 16];
__device__ float d_dual[NN * 16];
__device__ float d_h0[NN * 16];
__device__ __half d_h1h[NP * 256];           // fp16 transformed features (agg2 gather)
__device__ __half d_Ah[NP * 256];            // fp16 activations for layer-2 MMA (pads stay 0)
__device__ float d_bufA[NN * 256];
__device__ float d_sa[NN * 16];
__device__ float d_da[NN * 16];
__device__ __half d_W2hi[256 * 256];         // W2^T split [n][k]  fp16 hi
__device__ __half d_W2lo[256 * 256];
__device__ __half d_W3hi[256 * 256];
__device__ __half d_W3lo[256 * 256];
__device__ float d_As[256];                  // combined att-src matrix [k][h]
__device__ float d_Ad[256];                  // combined att-dst matrix [k][h]
__device__ int   d_mark[NN];                 // zero-init; compact resets to 0
__device__ int   d_list[NN];
__device__ int   d_listcnt;

// ================= merged SETUP: prepW | count | gemmA | attprep =================
#define SB_PREPW 512
#define SB_COUNT 782
#define SB_GEMMA 1024
#define SB_TOTAL (SB_PREPW + SB_COUNT + SB_GEMMA + 2)

__global__ void k_setup(const float* __restrict__ W2, const float* __restrict__ W3,
                        const int* __restrict__ dst,
                        const float* __restrict__ hd, const float* __restrict__ wr,
                        const float* __restrict__ W1,
                        const float* __restrict__ a1s, const float* __restrict__ a1d) {
    int bid = blockIdx.x, tid = threadIdx.x;
    if (bid < SB_PREPW) {
        int idx = bid * 256 + tid;
        int sel = idx >> 16;
        int r = idx & 65535;
        int n = r >> 8, k = r & 255;
        float w = (sel ? W3 : W2)[k * 256 + n];
        __half h = __float2half_rn(w);
        __half l = __float2half_rn(w - __half2float(h));
        if (sel) { d_W3hi[r] = h; d_W3lo[r] = l; }
        else     { d_W2hi[r] = h; d_W2lo[r] = l; }
    } else if (bid < SB_PREPW + SB_COUNT) {
        int t = (bid - SB_PREPW) * 256 + tid;
        int e0 = t * 4;
        if (e0 + 3 < EE) {
            int4 d4 = *(const int4*)(dst + e0);
            atomicAdd(&d_deg[d4.x], 1);
            atomicAdd(&d_deg[d4.y], 1);
            atomicAdd(&d_deg[d4.z], 1);
            atomicAdd(&d_deg[d4.w], 1);
        } else {
            for (int e = e0; e < EE; e++) atomicAdd(&d_deg[dst[e]], 1);
        }
    } else if (bid < SB_PREPW + SB_COUNT + SB_GEMMA) {
        int w = ((bid - SB_PREPW - SB_COUNT) * 256 + tid) >> 5;
        int lane = tid & 31;
        int i = w >> 4, j = w & 15;
        float a = 0.f;
#pragma unroll
        for (int kk = 0; kk < 16; kk++) {
            int k = lane + kk * 32;
            a += hd[i * 512 + k] * wr[k * 16 + j];
        }
#pragma unroll
        for (int off = 16; off >= 1; off >>= 1)
            a += __shfl_down_sync(0xffffffffu, a, off);
        if (lane == 0) d_T2[w] = a;
    } else {
        // attprep: As/Ad[k][h] = sum_c W1[k][h*16+c] * a_{src,dst}[h*16+c]
        int which = bid - (SB_PREPW + SB_COUNT + SB_GEMMA);
        int k = tid >> 4, h = tid & 15;
        const float* av = which ? a1d : a1s;
        float s = 0.f;
#pragma unroll
        for (int c = 0; c < 16; c++)
            s += W1[k * 256 + h * 16 + c] * av[h * 16 + c];
        (which ? d_Ad : d_As)[k * 16 + h] = s;
    }
}

// ================= merged PHASE2: scan (block 0) | gemmB =================
__global__ void __launch_bounds__(1024)
k_phase2(const float* __restrict__ wd) {
    if (blockIdx.x == 0) {
        __shared__ int warp_sums[32];
        int t = threadIdx.x;
        const int S = 49;
        int b0 = t * S;
        int sum = 0;
        for (int i = 0; i < S; i++) {
            int idx = b0 + i;
            if (idx < NN) sum += d_deg[idx] + 1;
        }
        int lane = t & 31, w = t >> 5;
        int v = sum;
#pragma unroll
        for (int off = 1; off < 32; off <<= 1) {
            int u = __shfl_up_sync(0xffffffffu, v, off);
            if (lane >= off) v += u;
        }
        if (lane == 31) warp_sums[w] = v;
        __syncthreads();
        if (w == 0) {
            int ws = warp_sums[lane];
#pragma unroll
            for (int off = 1; off < 32; off <<= 1) {
                int u = __shfl_up_sync(0xffffffffu, ws, off);
                if (lane >= off) ws += u;
            }
            warp_sums[lane] = ws;
        }
        __syncthreads();
        int ex = v - sum + (w > 0 ? warp_sums[w - 1] : 0);
        int run = ex;
        for (int i = 0; i < S; i++) {
            int idx = b0 + i;
            if (idx < NN) {
                int dg = d_deg[idx] + 1;
                d_deg[idx] = 0;
                run += dg;
                d_rowoff[idx + 1] = run;
                d_dis[idx] = rsqrtf((float)dg);
            }
        }
        if (t == 0) d_rowoff[0] = 0;
    } else {
        int w = (blockIdx.x - 1) * 32 + (threadIdx.x >> 5);
        int lane = threadIdx.x & 31;
        int i = w >> 4, j = w & 15;
        float a = 0.f;
#pragma unroll
        for (int kk = 0; kk < 16; kk++) {
            int k = lane + kk * 32;
            a += wd[i * 512 + k] * d_T2[k * 16 + j];
        }
#pragma unroll
        for (int off = 16; off >= 1; off >>= 1)
            a += __shfl_down_sync(0xffffffffu, a, off);
        if (lane == 0) d_M[w] = a;
    }
}

// ================= merged PHASE3: scatter | xw_dual =================
#define PB_SCAT ((ET + 255) / 256)
#define PB_XW (NN / 16)
#define PB_TOTAL (PB_SCAT + PB_XW)

__global__ void __launch_bounds__(256)
k_phase3(const int* __restrict__ ei, const float* __restrict__ x,
         const float* __restrict__ Wg) {
    int bid = blockIdx.x, tid = threadIdx.x;
    if (bid < PB_SCAT) {
        int e = bid * 256 + tid;
        if (e >= ET) return;
        int s, dd;
        if (e < EE) { s = ei[e]; dd = ei[EE + e]; }
        else        { s = dd = e - EE; }
        int p = atomicAdd(&d_cursor[dd], 1);
        d_csr[d_rowoff[dd] + p] = s;
    } else {
        __shared__ float sx[16][132];
        int nb = (bid - PB_SCAT) * 16;
        const float4* xs = (const float4*)(x + (size_t)nb * 128);
        for (int i = tid; i < 512; i += 256) {
            float4 v = xs[i];
            int r = i >> 5, c = (i & 31) * 4;
            sx[r][c] = v.x; sx[r][c + 1] = v.y; sx[r][c + 2] = v.z; sx[r][c + 3] = v.w;
        }
        __syncthreads();
        int nl = tid >> 4, j = tid & 15;
        float a = 0.f, b = 0.f;
#pragma unroll 4
        for (int k = 0; k < 128; k++) {
            float xv = sx[nl][k];
            a += xv * Wg[k * 16 + j];
            b += xv * d_M[k * 16 + j];
        }
        int n = nb + nl;
        d_xw[n * 16 + j] = a;
        d_dual[n * 16 + j] = b;
    }
}

// === merged: GCN agg (float4 ch, 4-edge unroll) + fused layer-1 sa/da | mark set ===
#define GB_GCN ((NN * 4 + 255) / 256)

__global__ void k_gcn_agg(const float* __restrict__ bg,
                          const int* __restrict__ ui, const int* __restrict__ ii,
                          int P) {
    int bid = blockIdx.x, tid = threadIdx.x;
    if (bid < GB_GCN) {
        int t = bid * 256 + tid;
        int g = t >> 2, c4 = t & 3;
        bool act = (g < NN);
        if (!act) g = NN - 1;          // clamp: all lanes participate in shfl
        int beg = d_rowoff[g], end = d_rowoff[g + 1];
        float4 acc = make_float4(0.f, 0.f, 0.f, 0.f);
        int e = beg;
        for (; e + 3 < end; e += 4) {
            int s0 = d_csr[e], s1 = d_csr[e + 1], s2 = d_csr[e + 2], s3 = d_csr[e + 3];
            float ds0 = d_dis[s0], ds1 = d_dis[s1], ds2 = d_dis[s2], ds3 = d_dis[s3];
            float4 x0 = ((const float4*)(d_xw + s0 * 16))[c4];
            float4 x1 = ((const float4*)(d_xw + s1 * 16))[c4];
            float4 x2 = ((const float4*)(d_xw + s2 * 16))[c4];
            float4 x3 = ((const float4*)(d_xw + s3 * 16))[c4];
            acc.x += ds0 * x0.x + ds1 * x1.x + ds2 * x2.x + ds3 * x3.x;
            acc.y += ds0 * x0.y + ds1 * x1.y + ds2 * x2.y + ds3 * x3.y;
            acc.z += ds0 * x0.z + ds1 * x1.z + ds2 * x2.z + ds3 * x3.z;
            acc.w += ds0 * x0.w + ds1 * x1.w + ds2 * x2.w + ds3 * x3.w;
        }
        for (; e < end; e++) {
            int s = d_csr[e];
            float ds = d_dis[s];
            float4 xw = ((const float4*)(d_xw + s * 16))[c4];
            acc.x += ds * xw.x; acc.y += ds * xw.y;
            acc.z += ds * xw.z; acc.w += ds * xw.w;
        }
        float dg = d_dis[g];
        float4 du = ((const float4*)(d_dual + g * 16))[c4];
        float vo[4];
        vo[0] = acc.x * dg + bg[c4 * 4 + 0] + du.x;
        vo[1] = acc.y * dg + bg[c4 * 4 + 1] + du.y;
        vo[2] = acc.z * dg + bg[c4 * 4 + 2] + du.z;
        vo[3] = acc.w * dg + bg[c4 * 4 + 3] + du.w;
#pragma unroll
        for (int j = 0; j < 4; j++)
            vo[j] = vo[j] > 0.f ? vo[j] : (__expf(vo[j]) - 1.f);
        if (act) {
            float4 st = make_float4(vo[0], vo[1], vo[2], vo[3]);
            ((float4*)(d_h0 + g * 16))[c4] = st;
            if (c4 == 0) d_cursor[g] = 0;   // reset for next replay
        }
        // fused layer-1 attention dots: sa/da[g][h] = h0[g] . As/Ad[:,h]
        float sap[16], dap[16];
#pragma unroll
        for (int h = 0; h < 16; h++) { sap[h] = 0.f; dap[h] = 0.f; }
#pragma unroll
        for (int j = 0; j < 4; j++) {
            float v = vo[j];
            const float* Ar = d_As + (c4 * 4 + j) * 16;
            const float* Dr = d_Ad + (c4 * 4 + j) * 16;
#pragma unroll
            for (int h = 0; h < 16; h++) {
                sap[h] += v * Ar[h];
                dap[h] += v * Dr[h];
            }
        }
#pragma unroll
        for (int h = 0; h < 16; h++) {
            sap[h] += __shfl_xor_sync(0xffffffffu, sap[h], 1, 4);
            sap[h] += __shfl_xor_sync(0xffffffffu, sap[h], 2, 4);
            dap[h] += __shfl_xor_sync(0xffffffffu, dap[h], 1, 4);
            dap[h] += __shfl_xor_sync(0xffffffffu, dap[h], 2, 4);
        }
        if (act && c4 == 0) {
#pragma unroll
            for (int h = 0; h < 16; h++) {
                d_sa[g * 16 + h] = sap[h];
                d_da[g * 16 + h] = dap[h];
            }
        }
    } else {
        int i = (bid - GB_GCN) * 256 + tid;
        if (i == 0) d_listcnt = 0;
        if (i < 2 * P) {
            int n = (i < P) ? ui[i] : ii[i - P];
            d_mark[n] = 1;
            int beg = d_rowoff[n], end = d_rowoff[n + 1];
            for (int e = beg; e < end; e++) d_mark[d_csr[e]] = 1;
        }
    }
}

// ====== layer-1 aggregation in h0-space + post-transform by W1 | compact tail ======
#define AB_AGG ((NN * 32) / 256)
#define AB_CMP ((NN + 255) / 256)

__global__ void __launch_bounds__(256)
k_agg1(const float* __restrict__ W1, const float* __restrict__ b) {
    int bid = blockIdx.x, tid = threadIdx.x;
    if (bid < AB_AGG) {
        __shared__ float sW1[16][264];
        for (int i = tid; i < 16 * 64; i += 256) {
            int k = i >> 6, c = i & 63;
            float4 v = ((const float4*)(W1 + k * 256))[c];
            *(float4*)&sW1[k][c * 4] = v;
        }
        __syncthreads();
        int n = (bid * 256 + tid) >> 5;
        int lane = tid & 31;
        int hd = lane >> 1, kh = lane & 1;
        float da_l = d_da[n * 16 + hd];
        int beg = d_rowoff[n], end = d_rowoff[n + 1];

        float m = -1e30f, z = 0.f;
        float acc[8];
#pragma unroll
        for (int i = 0; i < 8; i++) acc[i] = 0.f;

        int e = beg;
        for (; e + 1 < end; e += 2) {
            int s0 = d_csr[e], s1 = d_csr[e + 1];
            float l0 = d_sa[s0 * 16 + hd] + da_l;
            float l1 = d_sa[s1 * 16 + hd] + da_l;
            float4 u0 = *(const float4*)(d_h0 + s0 * 16 + kh * 8);
            float4 u1 = *(const float4*)(d_h0 + s0 * 16 + kh * 8 + 4);
            float4 w0 = *(const float4*)(d_h0 + s1 * 16 + kh * 8);
            float4 w1 = *(const float4*)(d_h0 + s1 * 16 + kh * 8 + 4);
            l0 = l0 > 0.f ? l0 : 0.2f * l0;
            l1 = l1 > 0.f ? l1 : 0.2f * l1;
            float nm = fmaxf(m, fmaxf(l0, l1));
            float sc = __expf(m - nm);
            float e0 = __expf(l0 - nm), e1 = __expf(l1 - nm);
            m = nm;
            z = z * sc + e0 + e1;
            acc[0] = acc[0] * sc + e0 * u0.x + e1 * w0.x;
            acc[1] = acc[1] * sc + e0 * u0.y + e1 * w0.y;
            acc[2] = acc[2] * sc + e0 * u0.z + e1 * w0.z;
            acc[3] = acc[3] * sc + e0 * u0.w + e1 * w0.w;
            acc[4] = acc[4] * sc + e0 * u1.x + e1 * w1.x;
            acc[5] = acc[5] * sc + e0 * u1.y + e1 * w1.y;
            acc[6] = acc[6] * sc + e0 * u1.z + e1 * w1.z;
            acc[7] = acc[7] * sc + e0 * u1.w + e1 * w1.w;
        }
        if (e < end) {
            int s0 = d_csr[e];
            float l0 = d_sa[s0 * 16 + hd] + da_l;
            float4 u0 = *(const float4*)(d_h0 + s0 * 16 + kh * 8);
            float4 u1 = *(const float4*)(d_h0 + s0 * 16 + kh * 8 + 4);
            l0 = l0 > 0.f ? l0 : 0.2f * l0;
            float nm = fmaxf(m, l0);
            float sc = __expf(m - nm);
            float e0 = __expf(l0 - nm);
            m = nm;
            z = z * sc + e0;
            acc[0] = acc[0] * sc + e0 * u0.x;
            acc[1] = acc[1] * sc + e0 * u0.y;
            acc[2] = acc[2] * sc + e0 * u0.z;
            acc[3] = acc[3] * sc + e0 * u0.w;
            acc[4] = acc[4] * sc + e0 * u1.x;
            acc[5] = acc[5] * sc + e0 * u1.y;
            acc[6] = acc[6] * sc + e0 * u1.z;
            acc[7] = acc[7] * sc + e0 * u1.w;
        }

        float invz = 1.f / (z + 1e-16f);
#pragma unroll
        for (int i = 0; i < 8; i++) acc[i] *= invz;

        // post-transform: out[ch] = sum_k wacc[k] * W1[k][hd*16+ch]
        // lane owns k-half kh; compute partials for both ch halves, exchange partner's.
        float pown[8], poth[8];
#pragma unroll
        for (int c = 0; c < 8; c++) { pown[c] = 0.f; poth[c] = 0.f; }
        int colOwn = hd * 16 + kh * 8;
        int colOth = hd * 16 + (kh ^ 1) * 8;
#pragma unroll
        for (int j = 0; j < 8; j++) {
            int row = kh * 8 + j;
            float wj = acc[j];
            float4 a0 = *(const float4*)&sW1[row][colOwn];
            float4 a1 = *(const float4*)&sW1[row][colOwn + 4];
            float4 o0 = *(const float4*)&sW1[row][colOth];
            float4 o1 = *(const float4*)&sW1[row][colOth + 4];
            pown[0] += wj * a0.x; pown[1] += wj * a0.y; pown[2] += wj * a0.z; pown[3] += wj * a0.w;
            pown[4] += wj * a1.x; pown[5] += wj * a1.y; pown[6] += wj * a1.z; pown[7] += wj * a1.w;
            poth[0] += wj * o0.x; poth[1] += wj * o0.y; poth[2] += wj * o0.z; poth[3] += wj * o0.w;
            poth[4] += wj * o1.x; poth[5] += wj * o1.y; poth[6] += wj * o1.z; poth[7] += wj * o1.w;
        }
        float vo[8];
#pragma unroll
        for (int c = 0; c < 8; c++) {
            float other = __shfl_xor_sync(0xffffffffu, poth[c], 1);
            float v = pown[c] + other + b[lane * 8 + c];
            vo[c] = v > 0.f ? v : (__expf(v) - 1.f);
        }
        __half2 h0p = __floats2half2_rn(vo[0], vo[1]);
        __half2 h1p = __floats2half2_rn(vo[2], vo[3]);
        __half2 h2p = __floats2half2_rn(vo[4], vo[5]);
        __half2 h3p = __floats2half2_rn(vo[6], vo[7]);
        uint4 pk;
        pk.x = *(unsigned*)&h0p; pk.y = *(unsigned*)&h1p;
        pk.z = *(unsigned*)&h2p; pk.w = *(unsigned*)&h3p;
        *(uint4*)&d_Ah[(size_t)n * 256 + lane * 8] = pk;
    } else {
        int i = (bid - AB_AGG) * 256 + tid;
        if (i < NN && d_mark[i]) {
            int pos = atomicAdd(&d_listcnt, 1);
            d_list[pos] = i;
            d_mark[i] = 0;
        }
    }
}

// ---------------- MMA helpers ----------------
#define MMA_F16(C, A0, A1, A2, A3, B0, B1)                                   \
    asm volatile(                                                            \
        "mma.sync.aligned.m16n8k16.row.col.f32.f16.f16.f32 "                 \
        "{%0,%1,%2,%3}, {%4,%5,%6,%7}, {%8,%9}, {%0,%1,%2,%3};\n"            \
        : "+f"(C[0]), "+f"(C[1]), "+f"(C[2]), "+f"(C[3])                     \
        : "r"(A0), "r"(A1), "r"(A2), "r"(A3), "r"(B0), "r"(B1))

#define LDSM4(R0, R1, R2, R3, ADDR)                                          \
    asm volatile("ldmatrix.sync.aligned.m8n8.x4.shared.b16 {%0,%1,%2,%3}, [%4];" \
        : "=r"(R0), "=r"(R1), "=r"(R2), "=r"(R3) : "r"(ADDR))

#define SMEM_MMA ((128 * PIT + 2 * 64 * PIT) * 2)

// mainloop + epilogue over one 64-col B slice; writes rows g0,g1 (-1 = skip)
static __device__ __forceinline__ void mma_core(__half* sA, __half* sBhi, __half* sBlo,
                                                int lane, int warp, int n0,
                                                const float* __restrict__ as_,
                                                const float* __restrict__ ad_,
                                                int g0, int g1) {
    float c[8][4];
#pragma unroll
    for (int t = 0; t < 8; t++)
#pragma unroll
        for (int j = 0; j < 4; j++) c[t][j] = 0.f;

    int rA = warp * 16 + (lane & 15);
    int kOff = (lane >> 4) << 3;
    unsigned aB = (unsigned)__cvta_generic_to_shared(sA + rA * PIT + kOff);
    int rB = lane & 15;
    unsigned bHiB = (unsigned)__cvta_generic_to_shared(sBhi + rB * PIT + kOff);
    unsigned bLoB = (unsigned)__cvta_generic_to_shared(sBlo + rB * PIT + kOff);

#pragma unroll 4
    for (int kc = 0; kc < 16; kc++) {
        unsigned ka = kc * 32;
        unsigned a0, a1, a2, a3;
        LDSM4(a0, a1, a2, a3, aB + ka);
#pragma unroll
        for (int p = 0; p < 4; p++) {
            unsigned boff = (unsigned)(p * 16 * PIT * 2) + ka;
            unsigned bh0, bh1, bh2, bh3, bl0, bl1, bl2, bl3;
            LDSM4(bh0, bh1, bh2, bh3, bHiB + boff);
            LDSM4(bl0, bl1, bl2, bl3, bLoB + boff);
            MMA_F16(c[2 * p],     a0, a1, a2, a3, bh0, bh2);
            MMA_F16(c[2 * p],     a0, a1, a2, a3, bl0, bl2);
            MMA_F16(c[2 * p + 1], a0, a1, a2, a3, bh1, bh3);
            MMA_F16(c[2 * p + 1], a0, a1, a2, a3, bl1, bl3);
        }
    }

    int H0 = n0 >> 4;
    int cbase = (lane & 3) * 2;
    float vs0[4] = {0, 0, 0, 0}, vd0[4] = {0, 0, 0, 0};
    float vs1[4] = {0, 0, 0, 0}, vd1[4] = {0, 0, 0, 0};
#pragma unroll
    for (int t = 0; t < 8; t++) {
        int col = n0 + t * 8 + cbase;
        if (g0 >= 0)
            *(__half2*)&d_h1h[(size_t)g0 * 256 + col] = __floats2half2_rn(c[t][0], c[t][1]);
        if (g1 >= 0)
            *(__half2*)&d_h1h[(size_t)g1 * 256 + col] = __floats2half2_rn(c[t][2], c[t][3]);
        float2 a2 = *(const float2*)&as_[col];
        float2 d2 = *(const float2*)&ad_[col];
        int hh = t >> 1;
        vs0[hh] += c[t][0] * a2.x + c[t][1] * a2.y;
        vd0[hh] += c[t][0] * d2.x + c[t][1] * d2.y;
        vs1[hh] += c[t][2] * a2.x + c[t][3] * a2.y;
        vd1[hh] += c[t][2] * d2.x + c[t][3] * d2.y;
    }
#pragma unroll
    for (int hh = 0; hh < 4; hh++) {
        vs0[hh] += __shfl_down_sync(0xffffffffu, vs0[hh], 2, 4);
        vs0[hh] += __shfl_down_sync(0xffffffffu, vs0[hh], 1, 4);
        vd0[hh] += __shfl_down_sync(0xffffffffu, vd0[hh], 2, 4);
        vd0[hh] += __shfl_down_sync(0xffffffffu, vd0[hh], 1, 4);
        vs1[hh] += __shfl_down_sync(0xffffffffu, vs1[hh], 2, 4);
        vs1[hh] += __shfl_down_sync(0xffffffffu, vs1[hh], 1, 4);
        vd1[hh] += __shfl_down_sync(0xffffffffu, vd1[hh], 2, 4);
        vd1[hh] += __shfl_down_sync(0xffffffffu, vd1[hh], 1, 4);
    }
    if ((lane & 3) == 0) {
        if (g0 >= 0 && g0 < NN) {
#pragma unroll
            for (int hh = 0; hh < 4; hh++) {
                d_sa[g0 * 16 + H0 + hh] = vs0[hh];
                d_da[g0 * 16 + H0 + hh] = vd0[hh];
            }
        }
        if (g1 >= 0 && g1 < NN) {
#pragma unroll
            for (int hh = 0; hh < 4; hh++) {
                d_sa[g1 * 16 + H0 + hh] = vs1[hh];
                d_da[g1 * 16 + H0 + hh] = vd1[hh];
            }
        }
    }
}

static __device__ __forceinline__ void stage_B(__half* sBhi, __half* sBlo,
                                               const __half* __restrict__ Bhi,
                                               const __half* __restrict__ Blo,
                                               int n0, int tid) {
    const uint4* bH = (const uint4*)(Bhi + (size_t)n0 * 256);
    const uint4* bL = (const uint4*)(Blo + (size_t)n0 * 256);
    for (int i = tid; i < 64 * 32; i += 256) {
        int r = i >> 5, c = i & 31;
        *(uint4*)(sBhi + r * PIT + c * 8) = bH[r * 32 + c];
        *(uint4*)(sBlo + r * PIT + c * 8) = bL[r * 32 + c];
    }
}

// layer-2: all rows; 2 sequential 64-col slices per block (A staged once)
__global__ void __launch_bounds__(256, 1)
k_transform_mma(const __half* __restrict__ Bhi, const __half* __restrict__ Blo,
                const float* __restrict__ as_, const float* __restrict__ ad_) {
    extern __shared__ __half sm[];
    __half* sA = sm;
    __half* sBhi = sA + 128 * PIT;
    __half* sBlo = sBhi + 64 * PIT;
    int tid = threadIdx.x, lane = tid & 31, warp = tid >> 5;
    int m0 = blockIdx.x * 128;
    {
        const uint4* gA = (const uint4*)(d_Ah + (size_t)m0 * 256);
        for (int i = tid; i < 128 * 32; i += 256) {
            int r = i >> 5, c = i & 31;
            *(uint4*)(sA + r * PIT + c * 8) = gA[r * 32 + c];
        }
    }
    int g0 = m0 + warp * 16 + (lane >> 2);
#pragma unroll
    for (int s = 0; s < 2; s++) {
        int n0 = blockIdx.y * 128 + s * 64;
        stage_B(sBhi, sBlo, Bhi, Blo, n0, tid);
        __syncthreads();
        mma_core(sA, sBhi, sBlo, lane, warp, n0, as_, ad_, g0, g0 + 8);
        __syncthreads();
    }
}

// layer-3: only listed rows (gather A by index, scatter outputs)
__global__ void __launch_bounds__(256, 1)
k_transform_mma_idx(const __half* __restrict__ Bhi, const __half* __restrict__ Blo,
                    const float* __restrict__ as_, const float* __restrict__ ad_) {
    extern __shared__ __half sm[];
    __shared__ int snode[128];
    __half* sA = sm;
    __half* sBhi = sA + 128 * PIT;
    __half* sBlo = sBhi + 64 * PIT;
    int tid = threadIdx.x, lane = tid & 31, warp = tid >> 5;
    int m0 = blockIdx.x * 128;
    int cnt = d_listcnt;
    if (m0 >= cnt) return;
    for (int i = tid; i < 128; i += 256) {
        int r = m0 + i;
        snode[i] = (r < cnt) ? d_list[r] : -1;
    }
    __syncthreads();
    for (int i = tid; i < 128 * 32; i += 256) {
        int r = i >> 5, c = i & 31;
        int nd = snode[r];
        uint4 v = make_uint4(0, 0, 0, 0);
        if (nd >= 0) v = ((const uint4*)(d_Ah + (size_t)nd * 256))[c];
        *(uint4*)(sA + r * PIT + c * 8) = v;
    }
    int r0 = warp * 16 + (lane >> 2);
#pragma unroll
    for (int s = 0; s < 2; s++) {
        int n0 = blockIdx.y * 128 + s * 64;
        stage_B(sBhi, sBlo, Bhi, Blo, n0, tid);
        __syncthreads();
        mma_core(sA, sBhi, sBlo, lane, warp, n0, as_, ad_, snode[r0], snode[r0 + 8]);
        __syncthreads();
    }
}

// ---------------- GAT aggregation body (256-dim gather): online softmax ----------------
template <bool SPLIT>
static __device__ __forceinline__ void gat_body(int n, int lane,
                                                const float* __restrict__ b,
                                                float* __restrict__ outf) {
    int hd = lane >> 1;
    float da_l = d_da[n * 16 + hd];
    int beg = d_rowoff[n], end = d_rowoff[n + 1];

    float m = -1e30f, z = 0.f;
    float acc[8];
#pragma unroll
    for (int i = 0; i < 8; i++) acc[i] = 0.f;

    int e = beg;
    for (; e + 3 < end; e += 4) {
        int s0 = d_csr[e], s1 = d_csr[e + 1], s2 = d_csr[e + 2], s3 = d_csr[e + 3];
        float l0 = d_sa[s0 * 16 + hd] + da_l;
        float l1 = d_sa[s1 * 16 + hd] + da_l;
        float l2 = d_sa[s2 * 16 + hd] + da_l;
        float l3 = d_sa[s3 * 16 + hd] + da_l;
        uint4 hv0 = *(const uint4*)(d_h1h + (size_t)s0 * 256 + lane * 8);
        uint4 hv1 = *(const uint4*)(d_h1h + (size_t)s1 * 256 + lane * 8);
        uint4 hv2 = *(const uint4*)(d_h1h + (size_t)s2 * 256 + lane * 8);
        uint4 hv3 = *(const uint4*)(d_h1h + (size_t)s3 * 256 + lane * 8);
        l0 = l0 > 0.f ? l0 : 0.2f * l0;
        l1 = l1 > 0.f ? l1 : 0.2f * l1;
        l2 = l2 > 0.f ? l2 : 0.2f * l2;
        l3 = l3 > 0.f ? l3 : 0.2f * l3;
        float nm = fmaxf(fmaxf(m, fmaxf(l0, l1)), fmaxf(l2, l3));
        float sc = __expf(m - nm);
        float e0 = __expf(l0 - nm), e1 = __expf(l1 - nm);
        float e2 = __expf(l2 - nm), e3 = __expf(l3 - nm);
        m = nm;
        z = z * sc + (e0 + e1) + (e2 + e3);
        float2 f0 = __half22float2(*(__half2*)&hv0.x), f1 = __half22float2(*(__half2*)&hv0.y);
        float2 f2 = __half22float2(*(__half2*)&hv0.z), f3 = __half22float2(*(__half2*)&hv0.w);
        float2 g0 = __half22float2(*(__half2*)&hv1.x), g1 = __half22float2(*(__half2*)&hv1.y);
        float2 g2 = __half22float2(*(__half2*)&hv1.z), g3 = __half22float2(*(__half2*)&hv1.w);
        float2 p0 = __half22float2(*(__half2*)&hv2.x), p1 = __half22float2(*(__half2*)&hv2.y);
        float2 p2 = __half22float2(*(__half2*)&hv2.z), p3 = __half22float2(*(__half2*)&hv2.w);
        float2 q0 = __half22float2(*(__half2*)&hv3.x), q1 = __half22float2(*(__half2*)&hv3.y);
        float2 q2 = __half22float2(*(__half2*)&hv3.z), q3 = __half22float2(*(__half2*)&hv3.w);
        acc[0] = acc[0] * sc + (e0 * f0.x + e1 * g0.x) + (e2 * p0.x + e3 * q0.x);
        acc[1] = acc[1] * sc + (e0 * f0.y + e1 * g0.y) + (e2 * p0.y + e3 * q0.y);
        acc[2] = acc[2] * sc + (e0 * f1.x + e1 * g1.x) + (e2 * p1.x + e3 * q1.x);
        acc[3] = acc[3] * sc + (e0 * f1.y + e1 * g1.y) + (e2 * p1.y + e3 * q1.y);
        acc[4] = acc[4] * sc + (e0 * f2.x + e1 * g2.x) + (e2 * p2.x + e3 * q2.x);
        acc[5] = acc[5] * sc + (e0 * f2.y + e1 * g2.y) + (e2 * p2.y + e3 * q2.y);
        acc[6] = acc[6] * sc + (e0 * f3.x + e1 * g3.x) + (e2 * p3.x + e3 * q3.x);
        acc[7] = acc[7] * sc + (e0 * f3.y + e1 * g3.y) + (e2 * p3.y + e3 * q3.y);
    }
    for (; e < end; e++) {
        int s0 = d_csr[e];
        float l0 = d_sa[s0 * 16 + hd] + da_l;
        uint4 hv0 = *(const uint4*)(d_h1h + (size_t)s0 * 256 + lane * 8);
        l0 = l0 > 0.f ? l0 : 0.2f * l0;
        float nm = fmaxf(m, l0);
        float sc = __expf(m - nm);
        float e0 = __expf(l0 - nm);
        m = nm;
        z = z * sc + e0;
        float2 f0 = __half22float2(*(__half2*)&hv0.x), f1 = __half22float2(*(__half2*)&hv0.y);
        float2 f2 = __half22float2(*(__half2*)&hv0.z), f3 = __half22float2(*(__half2*)&hv0.w);
        acc[0] = acc[0] * sc + e0 * f0.x;
        acc[1] = acc[1] * sc + e0 * f0.y;
        acc[2] = acc[2] * sc + e0 * f1.x;
        acc[3] = acc[3] * sc + e0 * f1.y;
        acc[4] = acc[4] * sc + e0 * f2.x;
        acc[5] = acc[5] * sc + e0 * f2.y;
        acc[6] = acc[6] * sc + e0 * f3.x;
        acc[7] = acc[7] * sc + e0 * f3.y;
    }

    float invz = 1.f / (z + 1e-16f);
    float vo[8];
#pragma unroll
    for (int i = 0; i < 8; i++) {
        float v = acc[i] * invz + b[lane * 8 + i];
        vo[i] = v > 0.f ? v : (__expf(v) - 1.f);
    }
    if (SPLIT) {
        __half2 h0 = __floats2half2_rn(vo[0], vo[1]);
        __half2 h1 = __floats2half2_rn(vo[2], vo[3]);
        __half2 h2 = __floats2half2_rn(vo[4], vo[5]);
        __half2 h3 = __floats2half2_rn(vo[6], vo[7]);
        uint4 pk;
        pk.x = *(unsigned*)&h0; pk.y = *(unsigned*)&h1;
        pk.z = *(unsigned*)&h2; pk.w = *(unsigned*)&h3;
        *(uint4*)&d_Ah[(size_t)n * 256 + lane * 8] = pk;
    } else {
        *(float4*)&outf[(size_t)n * 256 + lane * 8] = make_float4(vo[0], vo[1], vo[2], vo[3]);
        *(float4*)&outf[(size_t)n * 256 + lane * 8 + 4] = make_float4(vo[4], vo[5], vo[6], vo[7]);
    }
}

// layer-2 agg: only listed nodes
__global__ void k_agg2_idx(const float* __restrict__ b) {
    int i = (blockIdx.x * blockDim.x + threadIdx.x) >> 5;
    if (i >= d_listcnt) return;
    gat_body<true>(d_list[i], threadIdx.x & 31, b, nullptr);
}

// layer-3: aggregate ONLY the user/item nodes
__global__ void k_gat_agg_list(const float* __restrict__ b, float* __restrict__ outf,
                               const int* __restrict__ ui, const int* __restrict__ ii,
                               int P) {
    int i = (blockIdx.x * blockDim.x + threadIdx.x) >> 5;
    if (i >= 2 * P) return;
    int n = (i < P) ? ui[i] : ii[i - P];
    gat_body<false>(n, threadIdx.x & 31, b, outf);
}

// ---------------- final ----------------
__global__ void k_final(const float* __restrict__ h, const int* __restrict__ ui,
                        const int* __restrict__ ii, const float* __restrict__ Wd,
                        float* __restrict__ out) {
    int p = (blockIdx.x * blockDim.x + threadIdx.x) >> 5;
    if (p >= 1024) return;
    int lane = threadIdx.x & 31;
    int u = ui[p], it = ii[p];
    float a0 = 0.f, a1 = 0.f;
    for (int k = lane; k < 256; k += 32) {
        float v = h[u * 256 + k];
        a0 += v * Wd[k * 2 + 0];
        a1 += v * Wd[k * 2 + 1];
        float w = h[it * 256 + k];
        a0 += w * Wd[(256 + k) * 2 + 0];
        a1 += w * Wd[(256 + k) * 2 + 1];
    }
#pragma unroll
    for (int off = 16; off >= 1; off >>= 1) {
        a0 += __shfl_down_sync(0xffffffffu, a0, off);
        a1 += __shfl_down_sync(0xffffffffu, a1, off);
    }
    if (lane == 0) {
        float mx = fmaxf(a0, a1);
        float lse = mx + __logf(__expf(a0 - mx) + __expf(a1 - mx));
        out[p * 2 + 0] = a0 - lse;
        out[p * 2 + 1] = a1 - lse;
    }
}

// ---------------- launcher ----------------
extern "C" void kernel_launch(void* const* d_in, const int* in_sizes, int n_in,
                              void* d_out, int out_size) {
    const float* x    = (const float*)d_in[0];
    const int*   ei   = (const int*)d_in[1];
    const float* Hd   = (const float*)d_in[2];
    const int*   ui   = (const int*)d_in[3];
    const int*   ii   = (const int*)d_in[4];
    const float* Wg   = (const float*)d_in[5];
    const float* bg   = (const float*)d_in[6];
    const float* W1   = (const float*)d_in[7];
    const float* a1s  = (const float*)d_in[8];
    const float* a1d  = (const float*)d_in[9];
    const float* b1   = (const float*)d_in[10];
    const float* W2   = (const float*)d_in[11];
    const float* a2s  = (const float*)d_in[12];
    const float* a2d  = (const float*)d_in[13];
    const float* b2   = (const float*)d_in[14];
    const float* W3   = (const float*)d_in[15];
    const float* a3s  = (const float*)d_in[16];
    const float* a3d  = (const float*)d_in[17];
    const float* b3   = (const float*)d_in[18];
    const float* wd   = (const float*)d_in[19];
    const float* wr   = (const float*)d_in[20];
    const float* wdnn = (const float*)d_in[21];
    float* out = (float*)d_out;

    int P = in_sizes[3];   // number of user/item pairs

    void *p_bufA, *p_w2hi, *p_w2lo, *p_w3hi, *p_w3lo;
    cudaGetSymbolAddress(&p_bufA, d_bufA);
    cudaGetSymbolAddress(&p_w2hi, d_W2hi);
    cudaGetSymbolAddress(&p_w2lo, d_W2lo);
    cudaGetSymbolAddress(&p_w3hi, d_W3hi);
    cudaGetSymbolAddress(&p_w3lo, d_W3lo);
    float* bufA = (float*)p_bufA;

    cudaFuncSetAttribute(k_transform_mma,
                         cudaFuncAttributeMaxDynamicSharedMemorySize, SMEM_MMA);
    cudaFuncSetAttribute(k_transform_mma_idx,
                         cudaFuncAttributeMaxDynamicSharedMemorySize, SMEM_MMA);

    k_setup<<<SB_TOTAL, 256>>>(W2, W3, ei + EE, Hd, wr, W1, a1s, a1d);
    k_phase2<<<65, 1024>>>(wd);
    k_phase3<<<PB_TOTAL, 256>>>(ei, x, Wg);
    k_gcn_agg<<<GB_GCN + (2 * P + 255) / 256, 256>>>(bg, ui, ii, P);

    // GAT layer 1: aggregate in h0-space + post-transform (W1) | compact tail
    k_agg1<<<AB_AGG + AB_CMP, 256>>>(W1, b1);

    // GAT layer 2: transform all nodes (A staged once per block, 2 B slices)
    k_transform_mma<<<dim3(NP / 128, 2), 256, SMEM_MMA>>>(
        (const __half*)p_w2hi, (const __half*)p_w2lo, a2s, a2d);
    k_agg2_idx<<<AB_AGG, 256>>>(b2);

    // GAT layer 3: transform only marked set (indexed), aggregate only listed nodes
    k_transform_mma_idx<<<dim3(NP / 128, 2), 256, SMEM_MMA>>>(
        (const __half*)p_w3hi, (const __half*)p_w3lo, a3s, a3d);
    k_gat_agg_list<<<(2 * P * 32 + 255) / 256, 256>>>(b3, bufA, ui, ii, P);

    k_final<<<(1024 * 32 + 255) / 256, 256>>>(bufA, ui, ii, wdnn, out);
}

// round 13
// speedup vs baseline: 1.0214x; 1.0214x over previous
#include <cuda_runtime.h>
#include <cuda_bf16.h>
#include <cuda_fp16.h>
#include <math.h>

#define NN 50000
#define NP 50048          // padded to 128
#define EE 800000
#define ET (EE + NN)      // edges + self loops
#define PIT 264           // smem row pitch (fp16): 33*16B -> LDSM conflict-free

// ---------------- scratch (device globals; no allocation allowed) ----------------
__device__ float d_T2[512 * 16];             // Hd @ Wr
__device__ float d_M[128 * 16];              // Wd @ T2
__device__ int   d_deg[NN];                  // starts 0; scan resets to 0 after use
__device__ int   d_rowoff[NN + 1];
__device__ int   d_cursor[NN];               // gcn_agg resets to 0 after scatter
__device__ float d_dis[NN];
__device__ int   d_csr[ET];
__device__ float d_xw[NN * 16];
__device__ float d_dual[NN * 16];
__device__ float d_h0[NN * 16];
__device__ __half d_h1h[NP * 256];           // fp16 transformed features (agg2 gather)
__device__ __half d_Ah[NP * 256];            // fp16 activations for layer-2 MMA (pads stay 0)
__device__ float d_bufA[NN * 256];
__device__ float d_sa[NN * 16];
__device__ float d_da[NN * 16];
__device__ __half d_W2hi[256 * 256];         // W2^T split [n][k]  fp16 hi
__device__ __half d_W2lo[256 * 256];
__device__ __half d_W3hi[256 * 256];
__device__ __half d_W3lo[256 * 256];
__device__ float d_As[256];                  // combined att-src matrix [k][h]
__device__ float d_Ad[256];                  // combined att-dst matrix [k][h]
__device__ int   d_mark[NN];                 // zero-init; compact resets to 0
__device__ int   d_list[NN];
__device__ int   d_listcnt;

// ================= merged SETUP: prepW | count | gemmA | attprep =================
#define SB_PREPW 512
#define SB_COUNT 782
#define SB_GEMMA 1024
#define SB_TOTAL (SB_PREPW + SB_COUNT + SB_GEMMA + 2)

__global__ void k_setup(const float* __restrict__ W2, const float* __restrict__ W3,
                        const int* __restrict__ dst,
                        const float* __restrict__ hd, const float* __restrict__ wr,
                        const float* __restrict__ W1,
                        const float* __restrict__ a1s, const float* __restrict__ a1d) {
    int bid = blockIdx.x, tid = threadIdx.x;
    if (bid < SB_PREPW) {
        int idx = bid * 256 + tid;
        int sel = idx >> 16;
        int r = idx & 65535;
        int n = r >> 8, k = r & 255;
        float w = (sel ? W3 : W2)[k * 256 + n];
        __half h = __float2half_rn(w);
        __half l = __float2half_rn(w - __half2float(h));
        if (sel) { d_W3hi[r] = h; d_W3lo[r] = l; }
        else     { d_W2hi[r] = h; d_W2lo[r] = l; }
    } else if (bid < SB_PREPW + SB_COUNT) {
        int t = (bid - SB_PREPW) * 256 + tid;
        int e0 = t * 4;
        if (e0 + 3 < EE) {
            int4 d4 = *(const int4*)(dst + e0);
            atomicAdd(&d_deg[d4.x], 1);
            atomicAdd(&d_deg[d4.y], 1);
            atomicAdd(&d_deg[d4.z], 1);
            atomicAdd(&d_deg[d4.w], 1);
        } else {
            for (int e = e0; e < EE; e++) atomicAdd(&d_deg[dst[e]], 1);
        }
    } else if (bid < SB_PREPW + SB_COUNT + SB_GEMMA) {
        int w = ((bid - SB_PREPW - SB_COUNT) * 256 + tid) >> 5;
        int lane = tid & 31;
        int i = w >> 4, j = w & 15;
        float a = 0.f;
#pragma unroll
        for (int kk = 0; kk < 16; kk++) {
            int k = lane + kk * 32;
            a += hd[i * 512 + k] * wr[k * 16 + j];
        }
#pragma unroll
        for (int off = 16; off >= 1; off >>= 1)
            a += __shfl_down_sync(0xffffffffu, a, off);
        if (lane == 0) d_T2[w] = a;
    } else {
        // attprep: As/Ad[k][h] = sum_c W1[k][h*16+c] * a_{src,dst}[h*16+c]
        int which = bid - (SB_PREPW + SB_COUNT + SB_GEMMA);
        int k = tid >> 4, h = tid & 15;
        const float* av = which ? a1d : a1s;
        float s = 0.f;
#pragma unroll
        for (int c = 0; c < 16; c++)
            s += W1[k * 256 + h * 16 + c] * av[h * 16 + c];
        (which ? d_Ad : d_As)[k * 16 + h] = s;
    }
}

// ================= merged PHASE2: scan (block 0) | gemmB =================
__global__ void __launch_bounds__(1024)
k_phase2(const float* __restrict__ wd) {
    if (blockIdx.x == 0) {
        __shared__ int warp_sums[32];
        int t = threadIdx.x;
        const int S = 49;
        int b0 = t * S;
        int sum = 0;
        for (int i = 0; i < S; i++) {
            int idx = b0 + i;
            if (idx < NN) sum += d_deg[idx] + 1;
        }
        int lane = t & 31, w = t >> 5;
        int v = sum;
#pragma unroll
        for (int off = 1; off < 32; off <<= 1) {
            int u = __shfl_up_sync(0xffffffffu, v, off);
            if (lane >= off) v += u;
        }
        if (lane == 31) warp_sums[w] = v;
        __syncthreads();
        if (w == 0) {
            int ws = warp_sums[lane];
#pragma unroll
            for (int off = 1; off < 32; off <<= 1) {
                int u = __shfl_up_sync(0xffffffffu, ws, off);
                if (lane >= off) ws += u;
            }
            warp_sums[lane] = ws;
        }
        __syncthreads();
        int ex = v - sum + (w > 0 ? warp_sums[w - 1] : 0);
        int run = ex;
        for (int i = 0; i < S; i++) {
            int idx = b0 + i;
            if (idx < NN) {
                int dg = d_deg[idx] + 1;
                d_deg[idx] = 0;
                run += dg;
                d_rowoff[idx + 1] = run;
                d_dis[idx] = rsqrtf((float)dg);
            }
        }
        if (t == 0) d_rowoff[0] = 0;
    } else {
        int w = (blockIdx.x - 1) * 32 + (threadIdx.x >> 5);
        int lane = threadIdx.x & 31;
        int i = w >> 4, j = w & 15;
        float a = 0.f;
#pragma unroll
        for (int kk = 0; kk < 16; kk++) {
            int k = lane + kk * 32;
            a += wd[i * 512 + k] * d_T2[k * 16 + j];
        }
#pragma unroll
        for (int off = 16; off >= 1; off >>= 1)
            a += __shfl_down_sync(0xffffffffu, a, off);
        if (lane == 0) d_M[w] = a;
    }
}

// ================= merged PHASE3: scatter | xw_dual =================
#define PB_SCAT ((ET + 255) / 256)
#define PB_XW (NN / 16)
#define PB_TOTAL (PB_SCAT + PB_XW)

__global__ void __launch_bounds__(256)
k_phase3(const int* __restrict__ ei, const float* __restrict__ x,
         const float* __restrict__ Wg) {
    int bid = blockIdx.x, tid = threadIdx.x;
    if (bid < PB_SCAT) {
        int e = bid * 256 + tid;
        if (e >= ET) return;
        int s, dd;
        if (e < EE) { s = ei[e]; dd = ei[EE + e]; }
        else        { s = dd = e - EE; }
        int p = atomicAdd(&d_cursor[dd], 1);
        d_csr[d_rowoff[dd] + p] = s;
    } else {
        __shared__ float sx[16][132];
        int nb = (bid - PB_SCAT) * 16;
        const float4* xs = (const float4*)(x + (size_t)nb * 128);
        for (int i = tid; i < 512; i += 256) {
            float4 v = xs[i];
            int r = i >> 5, c = (i & 31) * 4;
            sx[r][c] = v.x; sx[r][c + 1] = v.y; sx[r][c + 2] = v.z; sx[r][c + 3] = v.w;
        }
        __syncthreads();
        int nl = tid >> 4, j = tid & 15;
        float a = 0.f, b = 0.f;
#pragma unroll 4
        for (int k = 0; k < 128; k++) {
            float xv = sx[nl][k];
            a += xv * Wg[k * 16 + j];
            b += xv * d_M[k * 16 + j];
        }
        int n = nb + nl;
        d_xw[n * 16 + j] = a;
        d_dual[n * 16 + j] = b;
    }
}

// ======= merged: GCN aggregation (lean, float4 channels, 4-edge unroll) | mark set =======
#define GB_GCN ((NN * 4 + 255) / 256)

__global__ void k_gcn_agg(const float* __restrict__ bg,
                          const int* __restrict__ ui, const int* __restrict__ ii,
                          int P) {
    int bid = blockIdx.x, tid = threadIdx.x;
    if (bid < GB_GCN) {
        int t = bid * 256 + tid;
        int g = t >> 2, c4 = t & 3;
        if (g >= NN) return;
        int beg = d_rowoff[g], end = d_rowoff[g + 1];
        float4 acc = make_float4(0.f, 0.f, 0.f, 0.f);
        int e = beg;
        for (; e + 3 < end; e += 4) {
            int s0 = d_csr[e], s1 = d_csr[e + 1], s2 = d_csr[e + 2], s3 = d_csr[e + 3];
            float ds0 = d_dis[s0], ds1 = d_dis[s1], ds2 = d_dis[s2], ds3 = d_dis[s3];
            float4 x0 = ((const float4*)(d_xw + s0 * 16))[c4];
            float4 x1 = ((const float4*)(d_xw + s1 * 16))[c4];
            float4 x2 = ((const float4*)(d_xw + s2 * 16))[c4];
            float4 x3 = ((const float4*)(d_xw + s3 * 16))[c4];
            acc.x += ds0 * x0.x + ds1 * x1.x + ds2 * x2.x + ds3 * x3.x;
            acc.y += ds0 * x0.y + ds1 * x1.y + ds2 * x2.y + ds3 * x3.y;
            acc.z += ds0 * x0.z + ds1 * x1.z + ds2 * x2.z + ds3 * x3.z;
            acc.w += ds0 * x0.w + ds1 * x1.w + ds2 * x2.w + ds3 * x3.w;
        }
        for (; e < end; e++) {
            int s = d_csr[e];
            float ds = d_dis[s];
            float4 xw = ((const float4*)(d_xw + s * 16))[c4];
            acc.x += ds * xw.x; acc.y += ds * xw.y;
            acc.z += ds * xw.z; acc.w += ds * xw.w;
        }
        float dg = d_dis[g];
        float4 du = ((const float4*)(d_dual + g * 16))[c4];
        float4 vo;
        vo.x = acc.x * dg + bg[c4 * 4 + 0] + du.x;
        vo.y = acc.y * dg + bg[c4 * 4 + 1] + du.y;
        vo.z = acc.z * dg + bg[c4 * 4 + 2] + du.z;
        vo.w = acc.w * dg + bg[c4 * 4 + 3] + du.w;
        vo.x = vo.x > 0.f ? vo.x : (__expf(vo.x) - 1.f);
        vo.y = vo.y > 0.f ? vo.y : (__expf(vo.y) - 1.f);
        vo.z = vo.z > 0.f ? vo.z : (__expf(vo.z) - 1.f);
        vo.w = vo.w > 0.f ? vo.w : (__expf(vo.w) - 1.f);
        ((float4*)(d_h0 + g * 16))[c4] = vo;
        if (c4 == 0) d_cursor[g] = 0;   // reset for next replay
    } else {
        int i = (bid - GB_GCN) * 256 + tid;
        if (i == 0) d_listcnt = 0;
        if (i < 2 * P) {
            int n = (i < P) ? ui[i] : ii[i - P];
            d_mark[n] = 1;
            int beg = d_rowoff[n], end = d_rowoff[n + 1];
            for (int e = beg; e < end; e++) d_mark[d_csr[e]] = 1;
        }
    }
}

// ---------------- layer-1 attention dots: sa/da = h0 @ As/Ad (tiny) ----------------
// NN is a multiple of 16: half-warp per node, lane h owns head h.
__global__ void __launch_bounds__(256)
k_attdot1() {
    __shared__ float sAs[256], sAd[256];
    int tid = threadIdx.x;
    sAs[tid] = d_As[tid];
    sAd[tid] = d_Ad[tid];
    __syncthreads();
    int n = blockIdx.x * 16 + (tid >> 4);
    int h = tid & 15;
    float v = d_h0[n * 16 + h];     // coalesced: lane h loads element h
    float sa = 0.f, da = 0.f;
#pragma unroll
    for (int k = 0; k < 16; k++) {
        float hv = __shfl_sync(0xffffffffu, v, k, 16);
        sa += hv * sAs[k * 16 + h];
        da += hv * sAd[k * 16 + h];
    }
    d_sa[n * 16 + h] = sa;
    d_da[n * 16 + h] = da;
}

// ====== layer-1 agg in h0-space (4-edge unroll) + post-transform by W1 | compact ======
#define AB_AGG ((NN * 32) / 256)
#define AB_CMP ((NN + 255) / 256)

__global__ void __launch_bounds__(256)
k_agg1(const float* __restrict__ W1, const float* __restrict__ b) {
    int bid = blockIdx.x, tid = threadIdx.x;
    if (bid < AB_AGG) {
        __shared__ float sW1[16][264];
        for (int i = tid; i < 16 * 64; i += 256) {
            int k = i >> 6, c = i & 63;
            float4 v = ((const float4*)(W1 + k * 256))[c];
            *(float4*)&sW1[k][c * 4] = v;
        }
        __syncthreads();
        int n = (bid * 256 + tid) >> 5;
        int lane = tid & 31;
        int hd = lane >> 1, kh = lane & 1;
        float da_l = d_da[n * 16 + hd];
        int beg = d_rowoff[n], end = d_rowoff[n + 1];

        float m = -1e30f, z = 0.f;
        float acc[8];
#pragma unroll
        for (int i = 0; i < 8; i++) acc[i] = 0.f;

        int e = beg;
        for (; e + 3 < end; e += 4) {
            int s0 = d_csr[e], s1 = d_csr[e + 1], s2 = d_csr[e + 2], s3 = d_csr[e + 3];
            float l0 = d_sa[s0 * 16 + hd] + da_l;
            float l1 = d_sa[s1 * 16 + hd] + da_l;
            float l2 = d_sa[s2 * 16 + hd] + da_l;
            float l3 = d_sa[s3 * 16 + hd] + da_l;
            float4 u0a = *(const float4*)(d_h0 + s0 * 16 + kh * 8);
            float4 u0b = *(const float4*)(d_h0 + s0 * 16 + kh * 8 + 4);
            float4 u1a = *(const float4*)(d_h0 + s1 * 16 + kh * 8);
            float4 u1b = *(const float4*)(d_h0 + s1 * 16 + kh * 8 + 4);
            float4 u2a = *(const float4*)(d_h0 + s2 * 16 + kh * 8);
            float4 u2b = *(const float4*)(d_h0 + s2 * 16 + kh * 8 + 4);
            float4 u3a = *(const float4*)(d_h0 + s3 * 16 + kh * 8);
            float4 u3b = *(const float4*)(d_h0 + s3 * 16 + kh * 8 + 4);
            l0 = l0 > 0.f ? l0 : 0.2f * l0;
            l1 = l1 > 0.f ? l1 : 0.2f * l1;
            l2 = l2 > 0.f ? l2 : 0.2f * l2;
            l3 = l3 > 0.f ? l3 : 0.2f * l3;
            float nm = fmaxf(fmaxf(m, fmaxf(l0, l1)), fmaxf(l2, l3));
            float sc = __expf(m - nm);
            float e0 = __expf(l0 - nm), e1 = __expf(l1 - nm);
            float e2 = __expf(l2 - nm), e3 = __expf(l3 - nm);
            m = nm;
            z = z * sc + (e0 + e1) + (e2 + e3);
            acc[0] = acc[0] * sc + (e0 * u0a.x + e1 * u1a.x) + (e2 * u2a.x + e3 * u3a.x);
            acc[1] = acc[1] * sc + (e0 * u0a.y + e1 * u1a.y) + (e2 * u2a.y + e3 * u3a.y);
            acc[2] = acc[2] * sc + (e0 * u0a.z + e1 * u1a.z) + (e2 * u2a.z + e3 * u3a.z);
            acc[3] = acc[3] * sc + (e0 * u0a.w + e1 * u1a.w) + (e2 * u2a.w + e3 * u3a.w);
            acc[4] = acc[4] * sc + (e0 * u0b.x + e1 * u1b.x) + (e2 * u2b.x + e3 * u3b.x);
            acc[5] = acc[5] * sc + (e0 * u0b.y + e1 * u1b.y) + (e2 * u2b.y + e3 * u3b.y);
            acc[6] = acc[6] * sc + (e0 * u0b.z + e1 * u1b.z) + (e2 * u2b.z + e3 * u3b.z);
            acc[7] = acc[7] * sc + (e0 * u0b.w + e1 * u1b.w) + (e2 * u2b.w + e3 * u3b.w);
        }
        for (; e < end; e++) {
            int s0 = d_csr[e];
            float l0 = d_sa[s0 * 16 + hd] + da_l;
            float4 u0a = *(const float4*)(d_h0 + s0 * 16 + kh * 8);
            float4 u0b = *(const float4*)(d_h0 + s0 * 16 + kh * 8 + 4);
            l0 = l0 > 0.f ? l0 : 0.2f * l0;
            float nm = fmaxf(m, l0);
            float sc = __expf(m - nm);
            float e0 = __expf(l0 - nm);
            m = nm;
            z = z * sc + e0;
            acc[0] = acc[0] * sc + e0 * u0a.x;
            acc[1] = acc[1] * sc + e0 * u0a.y;
            acc[2] = acc[2] * sc + e0 * u0a.z;
            acc[3] = acc[3] * sc + e0 * u0a.w;
            acc[4] = acc[4] * sc + e0 * u0b.x;
            acc[5] = acc[5] * sc + e0 * u0b.y;
            acc[6] = acc[6] * sc + e0 * u0b.z;
            acc[7] = acc[7] * sc + e0 * u0b.w;
        }

        float invz = 1.f / (z + 1e-16f);
#pragma unroll
        for (int i = 0; i < 8; i++) acc[i] *= invz;

        // post-transform: out[ch] = sum_k wacc[k] * W1[k][hd*16+ch]
        float pown[8], poth[8];
#pragma unroll
        for (int c = 0; c < 8; c++) { pown[c] = 0.f; poth[c] = 0.f; }
        int colOwn = hd * 16 + kh * 8;
        int colOth = hd * 16 + (kh ^ 1) * 8;
#pragma unroll
        for (int j = 0; j < 8; j++) {
            int row = kh * 8 + j;
            float wj = acc[j];
            float4 a0 = *(const float4*)&sW1[row][colOwn];
            float4 a1 = *(const float4*)&sW1[row][colOwn + 4];
            float4 o0 = *(const float4*)&sW1[row][colOth];
            float4 o1 = *(const float4*)&sW1[row][colOth + 4];
            pown[0] += wj * a0.x; pown[1] += wj * a0.y; pown[2] += wj * a0.z; pown[3] += wj * a0.w;
            pown[4] += wj * a1.x; pown[5] += wj * a1.y; pown[6] += wj * a1.z; pown[7] += wj * a1.w;
            poth[0] += wj * o0.x; poth[1] += wj * o0.y; poth[2] += wj * o0.z; poth[3] += wj * o0.w;
            poth[4] += wj * o1.x; poth[5] += wj * o1.y; poth[6] += wj * o1.z; poth[7] += wj * o1.w;
        }
        float vo[8];
#pragma unroll
        for (int c = 0; c < 8; c++) {
            float other = __shfl_xor_sync(0xffffffffu, poth[c], 1);
            float v = pown[c] + other + b[lane * 8 + c];
            vo[c] = v > 0.f ? v : (__expf(v) - 1.f);
        }
        __half2 h0p = __floats2half2_rn(vo[0], vo[1]);
        __half2 h1p = __floats2half2_rn(vo[2], vo[3]);
        __half2 h2p = __floats2half2_rn(vo[4], vo[5]);
        __half2 h3p = __floats2half2_rn(vo[6], vo[7]);
        uint4 pk;
        pk.x = *(unsigned*)&h0p; pk.y = *(unsigned*)&h1p;
        pk.z = *(unsigned*)&h2p; pk.w = *(unsigned*)&h3p;
        *(uint4*)&d_Ah[(size_t)n * 256 + lane * 8] = pk;
    } else {
        int i = (bid - AB_AGG) * 256 + tid;
        if (i < NN && d_mark[i]) {
            int pos = atomicAdd(&d_listcnt, 1);
            d_list[pos] = i;
            d_mark[i] = 0;
        }
    }
}

// ---------------- MMA helpers ----------------
#define MMA_F16(C, A0, A1, A2, A3, B0, B1)                                   \
    asm volatile(                                                            \
        "mma.sync.aligned.m16n8k16.row.col.f32.f16.f16.f32 "                 \
        "{%0,%1,%2,%3}, {%4,%5,%6,%7}, {%8,%9}, {%0,%1,%2,%3};\n"            \
        : "+f"(C[0]), "+f"(C[1]), "+f"(C[2]), "+f"(C[3])                     \
        : "r"(A0), "r"(A1), "r"(A2), "r"(A3), "r"(B0), "r"(B1))

#define LDSM4(R0, R1, R2, R3, ADDR)                                          \
    asm volatile("ldmatrix.sync.aligned.m8n8.x4.shared.b16 {%0,%1,%2,%3}, [%4];" \
        : "=r"(R0), "=r"(R1), "=r"(R2), "=r"(R3) : "r"(ADDR))

#define SMEM_MMA ((128 * PIT + 2 * 64 * PIT) * 2)

// mainloop + epilogue over one 64-col B slice; writes rows g0,g1 (-1 = skip)
static __device__ __forceinline__ void mma_core(__half* sA, __half* sBhi, __half* sBlo,
                                                int lane, int warp, int n0,
                                                const float* __restrict__ as_,
                                                const float* __restrict__ ad_,
                                                int g0, int g1) {
    float c[8][4];
#pragma unroll
    for (int t = 0; t < 8; t++)
#pragma unroll
        for (int j = 0; j < 4; j++) c[t][j] = 0.f;

    int rA = warp * 16 + (lane & 15);
    int kOff = (lane >> 4) << 3;
    unsigned aB = (unsigned)__cvta_generic_to_shared(sA + rA * PIT + kOff);
    int rB = lane & 15;
    unsigned bHiB = (unsigned)__cvta_generic_to_shared(sBhi + rB * PIT + kOff);
    unsigned bLoB = (unsigned)__cvta_generic_to_shared(sBlo + rB * PIT + kOff);

#pragma unroll 4
    for (int kc = 0; kc < 16; kc++) {
        unsigned ka = kc * 32;
        unsigned a0, a1, a2, a3;
        LDSM4(a0, a1, a2, a3, aB + ka);
#pragma unroll
        for (int p = 0; p < 4; p++) {
            unsigned boff = (unsigned)(p * 16 * PIT * 2) + ka;
            unsigned bh0, bh1, bh2, bh3, bl0, bl1, bl2, bl3;
            LDSM4(bh0, bh1, bh2, bh3, bHiB + boff);
            LDSM4(bl0, bl1, bl2, bl3, bLoB + boff);
            MMA_F16(c[2 * p],     a0, a1, a2, a3, bh0, bh2);
            MMA_F16(c[2 * p],     a0, a1, a2, a3, bl0, bl2);
            MMA_F16(c[2 * p + 1], a0, a1, a2, a3, bh1, bh3);
            MMA_F16(c[2 * p + 1], a0, a1, a2, a3, bl1, bl3);
        }
    }

    int H0 = n0 >> 4;
    int cbase = (lane & 3) * 2;
    float vs0[4] = {0, 0, 0, 0}, vd0[4] = {0, 0, 0, 0};
    float vs1[4] = {0, 0, 0, 0}, vd1[4] = {0, 0, 0, 0};
#pragma unroll
    for (int t = 0; t < 8; t++) {
        int col = n0 + t * 8 + cbase;
        if (g0 >= 0)
            *(__half2*)&d_h1h[(size_t)g0 * 256 + col] = __floats2half2_rn(c[t][0], c[t][1]);
        if (g1 >= 0)
            *(__half2*)&d_h1h[(size_t)g1 * 256 + col] = __floats2half2_rn(c[t][2], c[t][3]);
        float2 a2 = *(const float2*)&as_[col];
        float2 d2 = *(const float2*)&ad_[col];
        int hh = t >> 1;
        vs0[hh] += c[t][0] * a2.x + c[t][1] * a2.y;
        vd0[hh] += c[t][0] * d2.x + c[t][1] * d2.y;
        vs1[hh] += c[t][2] * a2.x + c[t][3] * a2.y;
        vd1[hh] += c[t][2] * d2.x + c[t][3] * d2.y;
    }
#pragma unroll
    for (int hh = 0; hh < 4; hh++) {
        vs0[hh] += __shfl_down_sync(0xffffffffu, vs0[hh], 2, 4);
        vs0[hh] += __shfl_down_sync(0xffffffffu, vs0[hh], 1, 4);
        vd0[hh] += __shfl_down_sync(0xffffffffu, vd0[hh], 2, 4);
        vd0[hh] += __shfl_down_sync(0xffffffffu, vd0[hh], 1, 4);
        vs1[hh] += __shfl_down_sync(0xffffffffu, vs1[hh], 2, 4);
        vs1[hh] += __shfl_down_sync(0xffffffffu, vs1[hh], 1, 4);
        vd1[hh] += __shfl_down_sync(0xffffffffu, vd1[hh], 2, 4);
        vd1[hh] += __shfl_down_sync(0xffffffffu, vd1[hh], 1, 4);
    }
    if ((lane & 3) == 0) {
        if (g0 >= 0 && g0 < NN) {
#pragma unroll
            for (int hh = 0; hh < 4; hh++) {
                d_sa[g0 * 16 + H0 + hh] = vs0[hh];
                d_da[g0 * 16 + H0 + hh] = vd0[hh];
            }
        }
        if (g1 >= 0 && g1 < NN) {
#pragma unroll
            for (int hh = 0; hh < 4; hh++) {
                d_sa[g1 * 16 + H0 + hh] = vs1[hh];
                d_da[g1 * 16 + H0 + hh] = vd1[hh];
            }
        }
    }
}

static __device__ __forceinline__ void stage_B(__half* sBhi, __half* sBlo,
                                               const __half* __restrict__ Bhi,
                                               const __half* __restrict__ Blo,
                                               int n0, int tid) {
    const uint4* bH = (const uint4*)(Bhi + (size_t)n0 * 256);
    const uint4* bL = (const uint4*)(Blo + (size_t)n0 * 256);
    for (int i = tid; i < 64 * 32; i += 256) {
        int r = i >> 5, c = i & 31;
        *(uint4*)(sBhi + r * PIT + c * 8) = bH[r * 32 + c];
        *(uint4*)(sBlo + r * PIT + c * 8) = bL[r * 32 + c];
    }
}

// layer-2: all rows; 2 sequential 64-col slices per block (A staged once)
__global__ void __launch_bounds__(256, 1)
k_transform_mma(const __half* __restrict__ Bhi, const __half* __restrict__ Blo,
                const float* __restrict__ as_, const float* __restrict__ ad_) {
    extern __shared__ __half sm[];
    __half* sA = sm;
    __half* sBhi = sA + 128 * PIT;
    __half* sBlo = sBhi + 64 * PIT;
    int tid = threadIdx.x, lane = tid & 31, warp = tid >> 5;
    int m0 = blockIdx.x * 128;
    {
        const uint4* gA = (const uint4*)(d_Ah + (size_t)m0 * 256);
        for (int i = tid; i < 128 * 32; i += 256) {
            int r = i >> 5, c = i & 31;
            *(uint4*)(sA + r * PIT + c * 8) = gA[r * 32 + c];
        }
    }
    int g0 = m0 + warp * 16 + (lane >> 2);
#pragma unroll
    for (int s = 0; s < 2; s++) {
        int n0 = blockIdx.y * 128 + s * 64;
        stage_B(sBhi, sBlo, Bhi, Blo, n0, tid);
        __syncthreads();
        mma_core(sA, sBhi, sBlo, lane, warp, n0, as_, ad_, g0, g0 + 8);
        __syncthreads();
    }
}

// layer-3: only listed rows (gather A by index, scatter outputs)
__global__ void __launch_bounds__(256, 1)
k_transform_mma_idx(const __half* __restrict__ Bhi, const __half* __restrict__ Blo,
                    const float* __restrict__ as_, const float* __restrict__ ad_) {
    extern __shared__ __half sm[];
    __shared__ int snode[128];
    __half* sA = sm;
    __half* sBhi = sA + 128 * PIT;
    __half* sBlo = sBhi + 64 * PIT;
    int tid = threadIdx.x, lane = tid & 31, warp = tid >> 5;
    int m0 = blockIdx.x * 128;
    int cnt = d_listcnt;
    if (m0 >= cnt) return;
    for (int i = tid; i < 128; i += 256) {
        int r = m0 + i;
        snode[i] = (r < cnt) ? d_list[r] : -1;
    }
    __syncthreads();
    for (int i = tid; i < 128 * 32; i += 256) {
        int r = i >> 5, c = i & 31;
        int nd = snode[r];
        uint4 v = make_uint4(0, 0, 0, 0);
        if (nd >= 0) v = ((const uint4*)(d_Ah + (size_t)nd * 256))[c];
        *(uint4*)(sA + r * PIT + c * 8) = v;
    }
    int r0 = warp * 16 + (lane >> 2);
#pragma unroll
    for (int s = 0; s < 2; s++) {
        int n0 = blockIdx.y * 128 + s * 64;
        stage_B(sBhi, sBlo, Bhi, Blo, n0, tid);
        __syncthreads();
        mma_core(sA, sBhi, sBlo, lane, warp, n0, as_, ad_, snode[r0], snode[r0 + 8]);
        __syncthreads();
    }
}

// ---------------- GAT aggregation body (256-dim gather): online softmax ----------------
template <bool SPLIT>
static __device__ __forceinline__ void gat_body(int n, int lane,
                                                const float* __restrict__ b,
                                                float* __restrict__ outf) {
    int hd = lane >> 1;
    float da_l = d_da[n * 16 + hd];
    int beg = d_rowoff[n], end = d_rowoff[n + 1];

    float m = -1e30f, z = 0.f;
    float acc[8];
#pragma unroll
    for (int i = 0; i < 8; i++) acc[i] = 0.f;

    int e = beg;
    for (; e + 3 < end; e += 4) {
        int s0 = d_csr[e], s1 = d_csr[e + 1], s2 = d_csr[e + 2], s3 = d_csr[e + 3];
        float l0 = d_sa[s0 * 16 + hd] + da_l;
        float l1 = d_sa[s1 * 16 + hd] + da_l;
        float l2 = d_sa[s2 * 16 + hd] + da_l;
        float l3 = d_sa[s3 * 16 + hd] + da_l;
        uint4 hv0 = *(const uint4*)(d_h1h + (size_t)s0 * 256 + lane * 8);
        uint4 hv1 = *(const uint4*)(d_h1h + (size_t)s1 * 256 + lane * 8);
        uint4 hv2 = *(const uint4*)(d_h1h + (size_t)s2 * 256 + lane * 8);
        uint4 hv3 = *(const uint4*)(d_h1h + (size_t)s3 * 256 + lane * 8);
        l0 = l0 > 0.f ? l0 : 0.2f * l0;
        l1 = l1 > 0.f ? l1 : 0.2f * l1;
        l2 = l2 > 0.f ? l2 : 0.2f * l2;
        l3 = l3 > 0.f ? l3 : 0.2f * l3;
        float nm = fmaxf(fmaxf(m, fmaxf(l0, l1)), fmaxf(l2, l3));
        float sc = __expf(m - nm);
        float e0 = __expf(l0 - nm), e1 = __expf(l1 - nm);
        float e2 = __expf(l2 - nm), e3 = __expf(l3 - nm);
        m = nm;
        z = z * sc + (e0 + e1) + (e2 + e3);
        float2 f0 = __half22float2(*(__half2*)&hv0.x), f1 = __half22float2(*(__half2*)&hv0.y);
        float2 f2 = __half22float2(*(__half2*)&hv0.z), f3 = __half22float2(*(__half2*)&hv0.w);
        float2 g0 = __half22float2(*(__half2*)&hv1.x), g1 = __half22float2(*(__half2*)&hv1.y);
        float2 g2 = __half22float2(*(__half2*)&hv1.z), g3 = __half22float2(*(__half2*)&hv1.w);
        float2 p0 = __half22float2(*(__half2*)&hv2.x), p1 = __half22float2(*(__half2*)&hv2.y);
        float2 p2 = __half22float2(*(__half2*)&hv2.z), p3 = __half22float2(*(__half2*)&hv2.w);
        float2 q0 = __half22float2(*(__half2*)&hv3.x), q1 = __half22float2(*(__half2*)&hv3.y);
        float2 q2 = __half22float2(*(__half2*)&hv3.z), q3 = __half22float2(*(__half2*)&hv3.w);
        acc[0] = acc[0] * sc + (e0 * f0.x + e1 * g0.x) + (e2 * p0.x + e3 * q0.x);
        acc[1] = acc[1] * sc + (e0 * f0.y + e1 * g0.y) + (e2 * p0.y + e3 * q0.y);
        acc[2] = acc[2] * sc + (e0 * f1.x + e1 * g1.x) + (e2 * p1.x + e3 * q1.x);
        acc[3] = acc[3] * sc + (e0 * f1.y + e1 * g1.y) + (e2 * p1.y + e3 * q1.y);
        acc[4] = acc[4] * sc + (e0 * f2.x + e1 * g2.x) + (e2 * p2.x + e3 * q2.x);
        acc[5] = acc[5] * sc + (e0 * f2.y + e1 * g2.y) + (e2 * p2.y + e3 * q2.y);
        acc[6] = acc[6] * sc + (e0 * f3.x + e1 * g3.x) + (e2 * p3.x + e3 * q3.x);
        acc[7] = acc[7] * sc + (e0 * f3.y + e1 * g3.y) + (e2 * p3.y + e3 * q3.y);
    }
    for (; e < end; e++) {
        int s0 = d_csr[e];
        float l0 = d_sa[s0 * 16 + hd] + da_l;
        uint4 hv0 = *(const uint4*)(d_h1h + (size_t)s0 * 256 + lane * 8);
        l0 = l0 > 0.f ? l0 : 0.2f * l0;
        float nm = fmaxf(m, l0);
        float sc = __expf(m - nm);
        float e0 = __expf(l0 - nm);
        m = nm;
        z = z * sc + e0;
        float2 f0 = __half22float2(*(__half2*)&hv0.x), f1 = __half22float2(*(__half2*)&hv0.y);
        float2 f2 = __half22float2(*(__half2*)&hv0.z), f3 = __half22float2(*(__half2*)&hv0.w);
        acc[0] = acc[0] * sc + e0 * f0.x;
        acc[1] = acc[1] * sc + e0 * f0.y;
        acc[2] = acc[2] * sc + e0 * f1.x;
        acc[3] = acc[3] * sc + e0 * f1.y;
        acc[4] = acc[4] * sc + e0 * f2.x;
        acc[5] = acc[5] * sc + e0 * f2.y;
        acc[6] = acc[6] * sc + e0 * f3.x;
        acc[7] = acc[7] * sc + e0 * f3.y;
    }

    float invz = 1.f / (z + 1e-16f);
    float vo[8];
#pragma unroll
    for (int i = 0; i < 8; i++) {
        float v = acc[i] * invz + b[lane * 8 + i];
        vo[i] = v > 0.f ? v : (__expf(v) - 1.f);
    }
    if (SPLIT) {
        __half2 h0 = __floats2half2_rn(vo[0], vo[1]);
        __half2 h1 = __floats2half2_rn(vo[2], vo[3]);
        __half2 h2 = __floats2half2_rn(vo[4], vo[5]);
        __half2 h3 = __floats2half2_rn(vo[6], vo[7]);
        uint4 pk;
        pk.x = *(unsigned*)&h0; pk.y = *(unsigned*)&h1;
        pk.z = *(unsigned*)&h2; pk.w = *(unsigned*)&h3;
        *(uint4*)&d_Ah[(size_t)n * 256 + lane * 8] = pk;
    } else {
        *(float4*)&outf[(size_t)n * 256 + lane * 8] = make_float4(vo[0], vo[1], vo[2], vo[3]);
        *(float4*)&outf[(size_t)n * 256 + lane * 8 + 4] = make_float4(vo[4], vo[5], vo[6], vo[7]);
    }
}

// layer-2 agg: only listed nodes
__global__ void k_agg2_idx(const float* __restrict__ b) {
    int i = (blockIdx.x * blockDim.x + threadIdx.x) >> 5;
    if (i >= d_listcnt) return;
    gat_body<true>(d_list[i], threadIdx.x & 31, b, nullptr);
}

// layer-3: aggregate ONLY the user/item nodes
__global__ void k_gat_agg_list(const float* __restrict__ b, float* __restrict__ outf,
                               const int* __restrict__ ui, const int* __restrict__ ii,
                               int P) {
    int i = (blockIdx.x * blockDim.x + threadIdx.x) >> 5;
    if (i >= 2 * P) return;
    int n = (i < P) ? ui[i] : ii[i - P];
    gat_body<false>(n, threadIdx.x & 31, b, outf);
}

// ---------------- final ----------------
__global__ void k_final(const float* __restrict__ h, const int* __restrict__ ui,
                        const int* __restrict__ ii, const float* __restrict__ Wd,
                        float* __restrict__ out) {
    int p = (blockIdx.x * blockDim.x + threadIdx.x) >> 5;
    if (p >= 1024) return;
    int lane = threadIdx.x & 31;
    int u = ui[p], it = ii[p];
    float a0 = 0.f, a1 = 0.f;
    for (int k = lane; k < 256; k += 32) {
        float v = h[u * 256 + k];
        a0 += v * Wd[k * 2 + 0];
        a1 += v * Wd[k * 2 + 1];
        float w = h[it * 256 + k];
        a0 += w * Wd[(256 + k) * 2 + 0];
        a1 += w * Wd[(256 + k) * 2 + 1];
    }
#pragma unroll
    for (int off = 16; off >= 1; off >>= 1) {
        a0 += __shfl_down_sync(0xffffffffu, a0, off);
        a1 += __shfl_down_sync(0xffffffffu, a1, off);
    }
    if (lane == 0) {
        float mx = fmaxf(a0, a1);
        float lse = mx + __logf(__expf(a0 - mx) + __expf(a1 - mx));
        out[p * 2 + 0] = a0 - lse;
        out[p * 2 + 1] = a1 - lse;
    }
}

// ---------------- launcher ----------------
extern "C" void kernel_launch(void* const* d_in, const int* in_sizes, int n_in,
                              void* d_out, int out_size) {
    const float* x    = (const float*)d_in[0];
    const int*   ei   = (const int*)d_in[1];
    const float* Hd   = (const float*)d_in[2];
    const int*   ui   = (const int*)d_in[3];
    const int*   ii   = (const int*)d_in[4];
    const float* Wg   = (const float*)d_in[5];
    const float* bg   = (const float*)d_in[6];
    const float* W1   = (const float*)d_in[7];
    const float* a1s  = (const float*)d_in[8];
    const float* a1d  = (const float*)d_in[9];
    const float* b1   = (const float*)d_in[10];
    const float* W2   = (const float*)d_in[11];
    const float* a2s  = (const float*)d_in[12];
    const float* a2d  = (const float*)d_in[13];
    const float* b2   = (const float*)d_in[14];
    const float* W3   = (const float*)d_in[15];
    const float* a3s  = (const float*)d_in[16];
    const float* a3d  = (const float*)d_in[17];
    const float* b3   = (const float*)d_in[18];
    const float* wd   = (const float*)d_in[19];
    const float* wr   = (const float*)d_in[20];
    const float* wdnn = (const float*)d_in[21];
    float* out = (float*)d_out;

    int P = in_sizes[3];   // number of user/item pairs

    void *p_bufA, *p_w2hi, *p_w2lo, *p_w3hi, *p_w3lo;
    cudaGetSymbolAddress(&p_bufA, d_bufA);
    cudaGetSymbolAddress(&p_w2hi, d_W2hi);
    cudaGetSymbolAddress(&p_w2lo, d_W2lo);
    cudaGetSymbolAddress(&p_w3hi, d_W3hi);
    cudaGetSymbolAddress(&p_w3lo, d_W3lo);
    float* bufA = (float*)p_bufA;

    cudaFuncSetAttribute(k_transform_mma,
                         cudaFuncAttributeMaxDynamicSharedMemorySize, SMEM_MMA);
    cudaFuncSetAttribute(k_transform_mma_idx,
                         cudaFuncAttributeMaxDynamicSharedMemorySize, SMEM_MMA);

    k_setup<<<SB_TOTAL, 256>>>(W2, W3, ei + EE, Hd, wr, W1, a1s, a1d);
    k_phase2<<<65, 1024>>>(wd);
    k_phase3<<<PB_TOTAL, 256>>>(ei, x, Wg);
    k_gcn_agg<<<GB_GCN + (2 * P + 255) / 256, 256>>>(bg, ui, ii, P);
    k_attdot1<<<NN / 16, 256>>>();

    // GAT layer 1: aggregate in h0-space (4-edge unroll) + post-transform | compact
    k_agg1<<<AB_AGG + AB_CMP, 256>>>(W1, b1);

    // GAT layer 2: transform all nodes (A staged once per block, 2 B slices)
    k_transform_mma<<<dim3(NP / 128, 2), 256, SMEM_MMA>>>(
        (const __half*)p_w2hi, (const __half*)p_w2lo, a2s, a2d);
    k_agg2_idx<<<AB_AGG, 256>>>(b2);

    // GAT layer 3: transform only marked set (indexed), aggregate only listed nodes
    k_transform_mma_idx<<<dim3(NP / 128, 2), 256, SMEM_MMA>>>(
        (const __half*)p_w3hi, (const __half*)p_w3lo, a3s, a3d);
    k_gat_agg_list<<<(2 * P * 32 + 255) / 256, 256>>>(b3, bufA, ui, ii, P);

    k_final<<<(1024 * 32 + 255) / 256, 256>>>(bufA, ui, ii, wdnn, out);
}

// round 14
// speedup vs baseline: 1.2571x; 1.2307x over previous
#include <cuda_runtime.h>
#include <cuda_bf16.h>
#include <cuda_fp16.h>
#include <math.h>

#define NN 50000
#define NP 50048          // padded to 128
#define EE 800000
#define ET (EE + NN)      // edges + self loops
#define PIT 264           // smem row pitch (fp16): 33*16B -> LDSM conflict-free

// ---------------- scratch (device globals; no allocation allowed) ----------------
__device__ float d_T2[512 * 16];             // Hd @ Wr
__device__ float d_M[128 * 16];              // Wd @ T2
__device__ int   d_deg[NN];                  // starts 0; scan resets to 0 after use
__device__ int   d_rowoff[NN + 1];
__device__ int   d_cursor[NN];               // gcn_agg resets to 0 after scatter
__device__ float d_dis[NN];
__device__ int   d_csr[ET];
__device__ float d_xw[NN * 16];
__device__ float d_dual[NN * 16];
__device__ float d_h0[NN * 16];
__device__ __half d_h1h[NP * 256];           // fp16 transformed features (agg gather)
__device__ __half d_Ah[NP * 256];            // fp16 activations for layer-2 MMA (pads stay 0)
__device__ float d_bufA[NN * 256];
__device__ float d_sa[NN * 16];
__device__ float d_da[NN * 16];
__device__ __half d_W2h[256 * 256];          // W2^T [n][k] fp16
__device__ __half d_W3h[256 * 256];
__device__ int   d_mark[NN];                 // zero-init; compact resets to 0
__device__ int   d_list[NN];
__device__ int   d_listcnt;

// ================= merged SETUP: prepW | count | gemmA =================
#define SB_PREPW 512
#define SB_COUNT 782
#define SB_GEMMA 1024
#define SB_TOTAL (SB_PREPW + SB_COUNT + SB_GEMMA)

__global__ void k_setup(const float* __restrict__ W2, const float* __restrict__ W3,
                        const int* __restrict__ dst,
                        const float* __restrict__ hd, const float* __restrict__ wr) {
    int bid = blockIdx.x, tid = threadIdx.x;
    if (bid < SB_PREPW) {
        int idx = bid * 256 + tid;
        int sel = idx >> 16;
        int r = idx & 65535;
        int n = r >> 8, k = r & 255;
        float w = (sel ? W3 : W2)[k * 256 + n];
        __half h = __float2half_rn(w);
        if (sel) d_W3h[r] = h;
        else     d_W2h[r] = h;
    } else if (bid < SB_PREPW + SB_COUNT) {
        int t = (bid - SB_PREPW) * 256 + tid;
        int e0 = t * 4;
        if (e0 + 3 < EE) {
            int4 d4 = *(const int4*)(dst + e0);
            atomicAdd(&d_deg[d4.x], 1);
            atomicAdd(&d_deg[d4.y], 1);
            atomicAdd(&d_deg[d4.z], 1);
            atomicAdd(&d_deg[d4.w], 1);
        } else {
            for (int e = e0; e < EE; e++) atomicAdd(&d_deg[dst[e]], 1);
        }
    } else {
        int w = ((bid - SB_PREPW - SB_COUNT) * 256 + tid) >> 5;
        int lane = tid & 31;
        int i = w >> 4, j = w & 15;
        float a = 0.f;
#pragma unroll
        for (int kk = 0; kk < 16; kk++) {
            int k = lane + kk * 32;
            a += hd[i * 512 + k] * wr[k * 16 + j];
        }
#pragma unroll
        for (int off = 16; off >= 1; off >>= 1)
            a += __shfl_down_sync(0xffffffffu, a, off);
        if (lane == 0) d_T2[w] = a;
    }
}

// ================= merged PHASE2: scan (block 0) | gemmB =================
__global__ void __launch_bounds__(1024)
k_phase2(const float* __restrict__ wd) {
    if (blockIdx.x == 0) {
        __shared__ int warp_sums[32];
        int t = threadIdx.x;
        const int S = 49;
        int b0 = t * S;
        int sum = 0;
        for (int i = 0; i < S; i++) {
            int idx = b0 + i;
            if (idx < NN) sum += d_deg[idx] + 1;
        }
        int lane = t & 31, w = t >> 5;
        int v = sum;
#pragma unroll
        for (int off = 1; off < 32; off <<= 1) {
            int u = __shfl_up_sync(0xffffffffu, v, off);
            if (lane >= off) v += u;
        }
        if (lane == 31) warp_sums[w] = v;
        __syncthreads();
        if (w == 0) {
            int ws = warp_sums[lane];
#pragma unroll
            for (int off = 1; off < 32; off <<= 1) {
                int u = __shfl_up_sync(0xffffffffu, ws, off);
                if (lane >= off) ws += u;
            }
            warp_sums[lane] = ws;
        }
        __syncthreads();
        int ex = v - sum + (w > 0 ? warp_sums[w - 1] : 0);
        int run = ex;
        for (int i = 0; i < S; i++) {
            int idx = b0 + i;
            if (idx < NN) {
                int dg = d_deg[idx] + 1;
                d_deg[idx] = 0;
                run += dg;
                d_rowoff[idx + 1] = run;
                d_dis[idx] = rsqrtf((float)dg);
            }
        }
        if (t == 0) d_rowoff[0] = 0;
    } else {
        int w = (blockIdx.x - 1) * 32 + (threadIdx.x >> 5);
        int lane = threadIdx.x & 31;
        int i = w >> 4, j = w & 15;
        float a = 0.f;
#pragma unroll
        for (int kk = 0; kk < 16; kk++) {
            int k = lane + kk * 32;
            a += wd[i * 512 + k] * d_T2[k * 16 + j];
        }
#pragma unroll
        for (int off = 16; off >= 1; off >>= 1)
            a += __shfl_down_sync(0xffffffffu, a, off);
        if (lane == 0) d_M[w] = a;
    }
}

// ================= merged PHASE3: scatter | xw_dual =================
#define PB_SCAT ((ET + 255) / 256)
#define PB_XW (NN / 16)
#define PB_TOTAL (PB_SCAT + PB_XW)

__global__ void __launch_bounds__(256)
k_phase3(const int* __restrict__ ei, const float* __restrict__ x,
         const float* __restrict__ Wg) {
    int bid = blockIdx.x, tid = threadIdx.x;
    if (bid < PB_SCAT) {
        int e = bid * 256 + tid;
        if (e >= ET) return;
        int s, dd;
        if (e < EE) { s = ei[e]; dd = ei[EE + e]; }
        else        { s = dd = e - EE; }
        int p = atomicAdd(&d_cursor[dd], 1);
        d_csr[d_rowoff[dd] + p] = s;
    } else {
        __shared__ float sx[16][132];
        int nb = (bid - PB_SCAT) * 16;
        const float4* xs = (const float4*)(x + (size_t)nb * 128);
        for (int i = tid; i < 512; i += 256) {
            float4 v = xs[i];
            int r = i >> 5, c = (i & 31) * 4;
            sx[r][c] = v.x; sx[r][c + 1] = v.y; sx[r][c + 2] = v.z; sx[r][c + 3] = v.w;
        }
        __syncthreads();
        int nl = tid >> 4, j = tid & 15;
        float a = 0.f, b = 0.f;
#pragma unroll 4
        for (int k = 0; k < 128; k++) {
            float xv = sx[nl][k];
            a += xv * Wg[k * 16 + j];
            b += xv * d_M[k * 16 + j];
        }
        int n = nb + nl;
        d_xw[n * 16 + j] = a;
        d_dual[n * 16 + j] = b;
    }
}

// ======= merged: GCN aggregation (lean, float4 channels, 4-edge unroll) | mark set =======
#define GB_GCN ((NN * 4 + 255) / 256)

__global__ void k_gcn_agg(const float* __restrict__ bg,
                          const int* __restrict__ ui, const int* __restrict__ ii,
                          int P) {
    int bid = blockIdx.x, tid = threadIdx.x;
    if (bid < GB_GCN) {
        int t = bid * 256 + tid;
        int g = t >> 2, c4 = t & 3;
        if (g >= NN) return;
        int beg = d_rowoff[g], end = d_rowoff[g + 1];
        float4 acc = make_float4(0.f, 0.f, 0.f, 0.f);
        int e = beg;
        for (; e + 3 < end; e += 4) {
            int s0 = d_csr[e], s1 = d_csr[e + 1], s2 = d_csr[e + 2], s3 = d_csr[e + 3];
            float ds0 = d_dis[s0], ds1 = d_dis[s1], ds2 = d_dis[s2], ds3 = d_dis[s3];
            float4 x0 = ((const float4*)(d_xw + s0 * 16))[c4];
            float4 x1 = ((const float4*)(d_xw + s1 * 16))[c4];
            float4 x2 = ((const float4*)(d_xw + s2 * 16))[c4];
            float4 x3 = ((const float4*)(d_xw + s3 * 16))[c4];
            acc.x += ds0 * x0.x + ds1 * x1.x + ds2 * x2.x + ds3 * x3.x;
            acc.y += ds0 * x0.y + ds1 * x1.y + ds2 * x2.y + ds3 * x3.y;
            acc.z += ds0 * x0.z + ds1 * x1.z + ds2 * x2.z + ds3 * x3.z;
            acc.w += ds0 * x0.w + ds1 * x1.w + ds2 * x2.w + ds3 * x3.w;
        }
        for (; e < end; e++) {
            int s = d_csr[e];
            float ds = d_dis[s];
            float4 xw = ((const float4*)(d_xw + s * 16))[c4];
            acc.x += ds * xw.x; acc.y += ds * xw.y;
            acc.z += ds * xw.z; acc.w += ds * xw.w;
        }
        float dg = d_dis[g];
        float4 du = ((const float4*)(d_dual + g * 16))[c4];
        float4 vo;
        vo.x = acc.x * dg + bg[c4 * 4 + 0] + du.x;
        vo.y = acc.y * dg + bg[c4 * 4 + 1] + du.y;
        vo.z = acc.z * dg + bg[c4 * 4 + 2] + du.z;
        vo.w = acc.w * dg + bg[c4 * 4 + 3] + du.w;
        vo.x = vo.x > 0.f ? vo.x : (__expf(vo.x) - 1.f);
        vo.y = vo.y > 0.f ? vo.y : (__expf(vo.y) - 1.f);
        vo.z = vo.z > 0.f ? vo.z : (__expf(vo.z) - 1.f);
        vo.w = vo.w > 0.f ? vo.w : (__expf(vo.w) - 1.f);
        ((float4*)(d_h0 + g * 16))[c4] = vo;
        if (c4 == 0) d_cursor[g] = 0;   // reset for next replay
    } else {
        int i = (bid - GB_GCN) * 256 + tid;
        if (i == 0) d_listcnt = 0;
        if (i < 2 * P) {
            int n = (i < P) ? ui[i] : ii[i - P];
            d_mark[n] = 1;
            int beg = d_rowoff[n], end = d_rowoff[n + 1];
            for (int e = beg; e < end; e++) d_mark[d_csr[e]] = 1;
        }
    }
}

// ---------------- GAT layer-1 transform (FIN=16, FFMA; writes fp16 h1) ----------------
__global__ void __launch_bounds__(128, 8)
k_transform16(const float* __restrict__ hin, const float* __restrict__ W,
              const float* __restrict__ asrc, const float* __restrict__ adst) {
    __shared__ float s[16][16];
    int tid = threadIdx.x;
    int nb = blockIdx.x * 16;
    const float4* hin4 = (const float4*)(hin + nb * 16);
    float4* s4 = (float4*)s;
    for (int t = tid; t < 16 * 16 / 4; t += 128) s4[t] = hin4[t];
    __syncthreads();

    int cg = tid & 63;
    int ng = tid >> 6;
    const float4* W4 = (const float4*)W;
    float4 acc[8];
#pragma unroll
    for (int r = 0; r < 8; r++) acc[r] = make_float4(0.f, 0.f, 0.f, 0.f);

#pragma unroll
    for (int k = 0; k < 16; k++) {
        float4 w = W4[k * 64 + cg];
#pragma unroll
        for (int r = 0; r < 8; r++) {
            float sv = s[ng * 8 + r][k];
            acc[r].x += sv * w.x; acc[r].y += sv * w.y;
            acc[r].z += sv * w.z; acc[r].w += sv * w.w;
        }
    }

    float4 as4 = ((const float4*)asrc)[cg];
    float4 ad4 = ((const float4*)adst)[cg];
#pragma unroll
    for (int r = 0; r < 8; r++) {
        int n = nb + ng * 8 + r;
        if (n >= NN) break;
        __half2 p0 = __floats2half2_rn(acc[r].x, acc[r].y);
        __half2 p1 = __floats2half2_rn(acc[r].z, acc[r].w);
        *(__half2*)&d_h1h[(size_t)n * 256 + cg * 4] = p0;
        *(__half2*)&d_h1h[(size_t)n * 256 + cg * 4 + 2] = p1;
        float vs = acc[r].x * as4.x + acc[r].y * as4.y + acc[r].z * as4.z + acc[r].w * as4.w;
        float vd = acc[r].x * ad4.x + acc[r].y * ad4.y + acc[r].z * ad4.z + acc[r].w * ad4.w;
        vs += __shfl_down_sync(0xffffffffu, vs, 2, 4);
        vs += __shfl_down_sync(0xffffffffu, vs, 1, 4);
        vd += __shfl_down_sync(0xffffffffu, vd, 2, 4);
        vd += __shfl_down_sync(0xffffffffu, vd, 1, 4);
        if ((cg & 3) == 0) {
            int h = cg >> 2;
            d_sa[n * 16 + h] = vs;
            d_da[n * 16 + h] = vd;
        }
    }
}

// ---------------- MMA helpers ----------------
#define MMA_F16(C, A0, A1, A2, A3, B0, B1)                                   \
    asm volatile(                                                            \
        "mma.sync.aligned.m16n8k16.row.col.f32.f16.f16.f32 "                 \
        "{%0,%1,%2,%3}, {%4,%5,%6,%7}, {%8,%9}, {%0,%1,%2,%3};\n"            \
        : "+f"(C[0]), "+f"(C[1]), "+f"(C[2]), "+f"(C[3])                     \
        : "r"(A0), "r"(A1), "r"(A2), "r"(A3), "r"(B0), "r"(B1))

#define LDSM4(R0, R1, R2, R3, ADDR)                                          \
    asm volatile("ldmatrix.sync.aligned.m8n8.x4.shared.b16 {%0,%1,%2,%3}, [%4];" \
        : "=r"(R0), "=r"(R1), "=r"(R2), "=r"(R3) : "r"(ADDR))

#define SMEM_MMA ((128 * PIT + 64 * PIT) * 2)

// mainloop + epilogue over one 64-col B slice; writes rows g0,g1 (-1 = skip)
static __device__ __forceinline__ void mma_core(__half* sA, __half* sB,
                                                int lane, int warp, int n0,
                                                const float* __restrict__ as_,
                                                const float* __restrict__ ad_,
                                                int g0, int g1) {
    float c[8][4];
#pragma unroll
    for (int t = 0; t < 8; t++)
#pragma unroll
        for (int j = 0; j < 4; j++) c[t][j] = 0.f;

    int rA = warp * 16 + (lane & 15);
    int kOff = (lane >> 4) << 3;
    unsigned aB = (unsigned)__cvta_generic_to_shared(sA + rA * PIT + kOff);
    int rB = lane & 15;
    unsigned bB = (unsigned)__cvta_generic_to_shared(sB + rB * PIT + kOff);

#pragma unroll 4
    for (int kc = 0; kc < 16; kc++) {
        unsigned ka = kc * 32;
        unsigned a0, a1, a2, a3;
        LDSM4(a0, a1, a2, a3, aB + ka);
#pragma unroll
        for (int p = 0; p < 4; p++) {
            unsigned boff = (unsigned)(p * 16 * PIT * 2) + ka;
            unsigned b0, b1, b2, b3;
            LDSM4(b0, b1, b2, b3, bB + boff);
            MMA_F16(c[2 * p],     a0, a1, a2, a3, b0, b2);
            MMA_F16(c[2 * p + 1], a0, a1, a2, a3, b1, b3);
        }
    }

    int H0 = n0 >> 4;
    int cbase = (lane & 3) * 2;
    float vs0[4] = {0, 0, 0, 0}, vd0[4] = {0, 0, 0, 0};
    float vs1[4] = {0, 0, 0, 0}, vd1[4] = {0, 0, 0, 0};
#pragma unroll
    for (int t = 0; t < 8; t++) {
        int col = n0 + t * 8 + cbase;
        if (g0 >= 0)
            *(__half2*)&d_h1h[(size_t)g0 * 256 + col] = __floats2half2_rn(c[t][0], c[t][1]);
        if (g1 >= 0)
            *(__half2*)&d_h1h[(size_t)g1 * 256 + col] = __floats2half2_rn(c[t][2], c[t][3]);
        float2 a2 = *(const float2*)&as_[col];
        float2 d2 = *(const float2*)&ad_[col];
        int hh = t >> 1;
        vs0[hh] += c[t][0] * a2.x + c[t][1] * a2.y;
        vd0[hh] += c[t][0] * d2.x + c[t][1] * d2.y;
        vs1[hh] += c[t][2] * a2.x + c[t][3] * a2.y;
        vd1[hh] += c[t][2] * d2.x + c[t][3] * d2.y;
    }
#pragma unroll
    for (int hh = 0; hh < 4; hh++) {
        vs0[hh] += __shfl_down_sync(0xffffffffu, vs0[hh], 2, 4);
        vs0[hh] += __shfl_down_sync(0xffffffffu, vs0[hh], 1, 4);
        vd0[hh] += __shfl_down_sync(0xffffffffu, vd0[hh], 2, 4);
        vd0[hh] += __shfl_down_sync(0xffffffffu, vd0[hh], 1, 4);
        vs1[hh] += __shfl_down_sync(0xffffffffu, vs1[hh], 2, 4);
        vs1[hh] += __shfl_down_sync(0xffffffffu, vs1[hh], 1, 4);
        vd1[hh] += __shfl_down_sync(0xffffffffu, vd1[hh], 2, 4);
        vd1[hh] += __shfl_down_sync(0xffffffffu, vd1[hh], 1, 4);
    }
    if ((lane & 3) == 0) {
        if (g0 >= 0 && g0 < NN) {
#pragma unroll
            for (int hh = 0; hh < 4; hh++) {
                d_sa[g0 * 16 + H0 + hh] = vs0[hh];
                d_da[g0 * 16 + H0 + hh] = vd0[hh];
            }
        }
        if (g1 >= 0 && g1 < NN) {
#pragma unroll
            for (int hh = 0; hh < 4; hh++) {
                d_sa[g1 * 16 + H0 + hh] = vs1[hh];
                d_da[g1 * 16 + H0 + hh] = vd1[hh];
            }
        }
    }
}

static __device__ __forceinline__ void stage_B(__half* sB, const __half* __restrict__ Bh,
                                               int n0, int tid) {
    const uint4* bH = (const uint4*)(Bh + (size_t)n0 * 256);
    for (int i = tid; i < 64 * 32; i += 256) {
        int r = i >> 5, c = i & 31;
        *(uint4*)(sB + r * PIT + c * 8) = bH[r * 32 + c];
    }
}

// layer-2: all rows; 2 sequential 64-col slices per block (A staged once)
__global__ void __launch_bounds__(256, 1)
k_transform_mma(const __half* __restrict__ Bh,
                const float* __restrict__ as_, const float* __restrict__ ad_) {
    extern __shared__ __half sm[];
    __half* sA = sm;
    __half* sB = sA + 128 * PIT;
    int tid = threadIdx.x, lane = tid & 31, warp = tid >> 5;
    int m0 = blockIdx.x * 128;
    {
        const uint4* gA = (const uint4*)(d_Ah + (size_t)m0 * 256);
        for (int i = tid; i < 128 * 32; i += 256) {
            int r = i >> 5, c = i & 31;
            *(uint4*)(sA + r * PIT + c * 8) = gA[r * 32 + c];
        }
    }
    int g0 = m0 + warp * 16 + (lane >> 2);
#pragma unroll
    for (int s = 0; s < 2; s++) {
        int n0 = blockIdx.y * 128 + s * 64;
        stage_B(sB, Bh, n0, tid);
        __syncthreads();
        mma_core(sA, sB, lane, warp, n0, as_, ad_, g0, g0 + 8);
        __syncthreads();
    }
}

// layer-3: only listed rows (gather A by index, scatter outputs)
__global__ void __launch_bounds__(256, 1)
k_transform_mma_idx(const __half* __restrict__ Bh,
                    const float* __restrict__ as_, const float* __restrict__ ad_) {
    extern __shared__ __half sm[];
    __shared__ int snode[128];
    __half* sA = sm;
    __half* sB = sA + 128 * PIT;
    int tid = threadIdx.x, lane = tid & 31, warp = tid >> 5;
    int m0 = blockIdx.x * 128;
    int cnt = d_listcnt;
    if (m0 >= cnt) return;
    for (int i = tid; i < 128; i += 256) {
        int r = m0 + i;
        snode[i] = (r < cnt) ? d_list[r] : -1;
    }
    __syncthreads();
    for (int i = tid; i < 128 * 32; i += 256) {
        int r = i >> 5, c = i & 31;
        int nd = snode[r];
        uint4 v = make_uint4(0, 0, 0, 0);
        if (nd >= 0) v = ((const uint4*)(d_Ah + (size_t)nd * 256))[c];
        *(uint4*)(sA + r * PIT + c * 8) = v;
    }
    int r0 = warp * 16 + (lane >> 2);
#pragma unroll
    for (int s = 0; s < 2; s++) {
        int n0 = blockIdx.y * 128 + s * 64;
        stage_B(sB, Bh, n0, tid);
        __syncthreads();
        mma_core(sA, sB, lane, warp, n0, as_, ad_, snode[r0], snode[r0 + 8]);
        __syncthreads();
    }
}

// ---------------- GAT aggregation body: 4-edge branchless online softmax ----------------
template <bool SPLIT>
static __device__ __forceinline__ void gat_body(int n, int lane,
                                                const float* __restrict__ b,
                                                float* __restrict__ outf) {
    int hd = lane >> 1;
    float da_l = d_da[n * 16 + hd];
    int beg = d_rowoff[n], end = d_rowoff[n + 1];

    float m = -1e30f, z = 0.f;
    float acc[8];
#pragma unroll
    for (int i = 0; i < 8; i++) acc[i] = 0.f;

    int e = beg;
    for (; e + 3 < end; e += 4) {
        int s0 = d_csr[e], s1 = d_csr[e + 1], s2 = d_csr[e + 2], s3 = d_csr[e + 3];
        float l0 = d_sa[s0 * 16 + hd] + da_l;
        float l1 = d_sa[s1 * 16 + hd] + da_l;
        float l2 = d_sa[s2 * 16 + hd] + da_l;
        float l3 = d_sa[s3 * 16 + hd] + da_l;
        uint4 hv0 = *(const uint4*)(d_h1h + (size_t)s0 * 256 + lane * 8);
        uint4 hv1 = *(const uint4*)(d_h1h + (size_t)s1 * 256 + lane * 8);
        uint4 hv2 = *(const uint4*)(d_h1h + (size_t)s2 * 256 + lane * 8);
        uint4 hv3 = *(const uint4*)(d_h1h + (size_t)s3 * 256 + lane * 8);
        l0 = l0 > 0.f ? l0 : 0.2f * l0;
        l1 = l1 > 0.f ? l1 : 0.2f * l1;
        l2 = l2 > 0.f ? l2 : 0.2f * l2;
        l3 = l3 > 0.f ? l3 : 0.2f * l3;
        float nm = fmaxf(fmaxf(m, fmaxf(l0, l1)), fmaxf(l2, l3));
        float sc = __expf(m - nm);
        float e0 = __expf(l0 - nm), e1 = __expf(l1 - nm);
        float e2 = __expf(l2 - nm), e3 = __expf(l3 - nm);
        m = nm;
        z = z * sc + (e0 + e1) + (e2 + e3);
        float2 f0 = __half22float2(*(__half2*)&hv0.x), f1 = __half22float2(*(__half2*)&hv0.y);
        float2 f2 = __half22float2(*(__half2*)&hv0.z), f3 = __half22float2(*(__half2*)&hv0.w);
        float2 g0 = __half22float2(*(__half2*)&hv1.x), g1 = __half22float2(*(__half2*)&hv1.y);
        float2 g2 = __half22float2(*(__half2*)&hv1.z), g3 = __half22float2(*(__half2*)&hv1.w);
        float2 p0 = __half22float2(*(__half2*)&hv2.x), p1 = __half22float2(*(__half2*)&hv2.y);
        float2 p2 = __half22float2(*(__half2*)&hv2.z), p3 = __half22float2(*(__half2*)&hv2.w);
        float2 q0 = __half22float2(*(__half2*)&hv3.x), q1 = __half22float2(*(__half2*)&hv3.y);
        float2 q2 = __half22float2(*(__half2*)&hv3.z), q3 = __half22float2(*(__half2*)&hv3.w);
        acc[0] = acc[0] * sc + (e0 * f0.x + e1 * g0.x) + (e2 * p0.x + e3 * q0.x);
        acc[1] = acc[1] * sc + (e0 * f0.y + e1 * g0.y) + (e2 * p0.y + e3 * q0.y);
        acc[2] = acc[2] * sc + (e0 * f1.x + e1 * g1.x) + (e2 * p1.x + e3 * q1.x);
        acc[3] = acc[3] * sc + (e0 * f1.y + e1 * g1.y) + (e2 * p1.y + e3 * q1.y);
        acc[4] = acc[4] * sc + (e0 * f2.x + e1 * g2.x) + (e2 * p2.x + e3 * q2.x);
        acc[5] = acc[5] * sc + (e0 * f2.y + e1 * g2.y) + (e2 * p2.y + e3 * q2.y);
        acc[6] = acc[6] * sc + (e0 * f3.x + e1 * g3.x) + (e2 * p3.x + e3 * q3.x);
        acc[7] = acc[7] * sc + (e0 * f3.y + e1 * g3.y) + (e2 * p3.y + e3 * q3.y);
    }
    for (; e < end; e++) {
        int s0 = d_csr[e];
        float l0 = d_sa[s0 * 16 + hd] + da_l;
        uint4 hv0 = *(const uint4*)(d_h1h + (size_t)s0 * 256 + lane * 8);
        l0 = l0 > 0.f ? l0 : 0.2f * l0;
        float nm = fmaxf(m, l0);
        float sc = __expf(m - nm);
        float e0 = __expf(l0 - nm);
        m = nm;
        z = z * sc + e0;
        float2 f0 = __half22float2(*(__half2*)&hv0.x), f1 = __half22float2(*(__half2*)&hv0.y);
        float2 f2 = __half22float2(*(__half2*)&hv0.z), f3 = __half22float2(*(__half2*)&hv0.w);
        acc[0] = acc[0] * sc + e0 * f0.x;
        acc[1] = acc[1] * sc + e0 * f0.y;
        acc[2] = acc[2] * sc + e0 * f1.x;
        acc[3] = acc[3] * sc + e0 * f1.y;
        acc[4] = acc[4] * sc + e0 * f2.x;
        acc[5] = acc[5] * sc + e0 * f2.y;
        acc[6] = acc[6] * sc + e0 * f3.x;
        acc[7] = acc[7] * sc + e0 * f3.y;
    }

    float invz = 1.f / (z + 1e-16f);
    float vo[8];
#pragma unroll
    for (int i = 0; i < 8; i++) {
        float v = acc[i] * invz + b[lane * 8 + i];
        vo[i] = v > 0.f ? v : (__expf(v) - 1.f);
    }
    if (SPLIT) {
        __half2 h0 = __floats2half2_rn(vo[0], vo[1]);
        __half2 h1 = __floats2half2_rn(vo[2], vo[3]);
        __half2 h2 = __floats2half2_rn(vo[4], vo[5]);
        __half2 h3 = __floats2half2_rn(vo[6], vo[7]);
        uint4 pk;
        pk.x = *(unsigned*)&h0; pk.y = *(unsigned*)&h1;
        pk.z = *(unsigned*)&h2; pk.w = *(unsigned*)&h3;
        *(uint4*)&d_Ah[(size_t)n * 256 + lane * 8] = pk;
    } else {
        *(float4*)&outf[(size_t)n * 256 + lane * 8] = make_float4(vo[0], vo[1], vo[2], vo[3]);
        *(float4*)&outf[(size_t)n * 256 + lane * 8 + 4] = make_float4(vo[4], vo[5], vo[6], vo[7]);
    }
}

// layer-1 agg (all nodes) | compact tail blocks
#define AB_AGG ((NN * 32) / 256)
#define AB_CMP ((NN + 255) / 256)

__global__ void k_agg1(const float* __restrict__ b) {
    int bid = blockIdx.x;
    if (bid < AB_AGG) {
        int n = (bid * 256 + threadIdx.x) >> 5;
        if (n >= NN) return;
        gat_body<true>(n, threadIdx.x & 31, b, nullptr);
    } else {
        int i = (bid - AB_AGG) * 256 + threadIdx.x;
        if (i < NN && d_mark[i]) {
            int pos = atomicAdd(&d_listcnt, 1);
            d_list[pos] = i;
            d_mark[i] = 0;
        }
    }
}

// layer-2 agg: only listed nodes
__global__ void k_agg2_idx(const float* __restrict__ b) {
    int i = (blockIdx.x * blockDim.x + threadIdx.x) >> 5;
    if (i >= d_listcnt) return;
    gat_body<true>(d_list[i], threadIdx.x & 31, b, nullptr);
}

// layer-3: aggregate ONLY the user/item nodes
__global__ void k_gat_agg_list(const float* __restrict__ b, float* __restrict__ outf,
                               const int* __restrict__ ui, const int* __restrict__ ii,
                               int P) {
    int i = (blockIdx.x * blockDim.x + threadIdx.x) >> 5;
    if (i >= 2 * P) return;
    int n = (i < P) ? ui[i] : ii[i - P];
    gat_body<false>(n, threadIdx.x & 31, b, outf);
}

// ---------------- final ----------------
__global__ void k_final(const float* __restrict__ h, const int* __restrict__ ui,
                        const int* __restrict__ ii, const float* __restrict__ Wd,
                        float* __restrict__ out) {
    int p = (blockIdx.x * blockDim.x + threadIdx.x) >> 5;
    if (p >= 1024) return;
    int lane = threadIdx.x & 31;
    int u = ui[p], it = ii[p];
    float a0 = 0.f, a1 = 0.f;
    for (int k = lane; k < 256; k += 32) {
        float v = h[u * 256 + k];
        a0 += v * Wd[k * 2 + 0];
        a1 += v * Wd[k * 2 + 1];
        float w = h[it * 256 + k];
        a0 += w * Wd[(256 + k) * 2 + 0];
        a1 += w * Wd[(256 + k) * 2 + 1];
    }
#pragma unroll
    for (int off = 16; off >= 1; off >>= 1) {
        a0 += __shfl_down_sync(0xffffffffu, a0, off);
        a1 += __shfl_down_sync(0xffffffffu, a1, off);
    }
    if (lane == 0) {
        float mx = fmaxf(a0, a1);
        float lse = mx + __logf(__expf(a0 - mx) + __expf(a1 - mx));
        out[p * 2 + 0] = a0 - lse;
        out[p * 2 + 1] = a1 - lse;
    }
}

// ---------------- launcher ----------------
extern "C" void kernel_launch(void* const* d_in, const int* in_sizes, int n_in,
                              void* d_out, int out_size) {
    const float* x    = (const float*)d_in[0];
    const int*   ei   = (const int*)d_in[1];
    const float* Hd   = (const float*)d_in[2];
    const int*   ui   = (const int*)d_in[3];
    const int*   ii   = (const int*)d_in[4];
    const float* Wg   = (const float*)d_in[5];
    const float* bg   = (const float*)d_in[6];
    const float* W1   = (const float*)d_in[7];
    const float* a1s  = (const float*)d_in[8];
    const float* a1d  = (const float*)d_in[9];
    const float* b1   = (const float*)d_in[10];
    const float* W2   = (const float*)d_in[11];
    const float* a2s  = (const float*)d_in[12];
    const float* a2d  = (const float*)d_in[13];
    const float* b2   = (const float*)d_in[14];
    const float* W3   = (const float*)d_in[15];
    const float* a3s  = (const float*)d_in[16];
    const float* a3d  = (const float*)d_in[17];
    const float* b3   = (const float*)d_in[18];
    const float* wd   = (const float*)d_in[19];
    const float* wr   = (const float*)d_in[20];
    const float* wdnn = (const float*)d_in[21];
    float* out = (float*)d_out;

    int P = in_sizes[3];   // number of user/item pairs

    void *p_h0, *p_bufA, *p_w2h, *p_w3h;
    cudaGetSymbolAddress(&p_h0, d_h0);
    cudaGetSymbolAddress(&p_bufA, d_bufA);
    cudaGetSymbolAddress(&p_w2h, d_W2h);
    cudaGetSymbolAddress(&p_w3h, d_W3h);
    float* h0   = (float*)p_h0;
    float* bufA = (float*)p_bufA;

    cudaFuncSetAttribute(k_transform_mma,
                         cudaFuncAttributeMaxDynamicSharedMemorySize, SMEM_MMA);
    cudaFuncSetAttribute(k_transform_mma_idx,
                         cudaFuncAttributeMaxDynamicSharedMemorySize, SMEM_MMA);

    k_setup<<<SB_TOTAL, 256>>>(W2, W3, ei + EE, Hd, wr);
    k_phase2<<<65, 1024>>>(wd);
    k_phase3<<<PB_TOTAL, 256>>>(ei, x, Wg);
    k_gcn_agg<<<GB_GCN + (2 * P + 255) / 256, 256>>>(bg, ui, ii, P);

    // GAT layer 1 (all nodes) + compact tail
    k_transform16<<<NN / 16, 128>>>(h0, W1, a1s, a1d);
    k_agg1<<<AB_AGG + AB_CMP, 256>>>(b1);

    // GAT layer 2: transform all nodes (A staged once per block, 2 B slices)
    k_transform_mma<<<dim3(NP / 128, 2), 256, SMEM_MMA>>>(
        (const __half*)p_w2h, a2s, a2d);
    k_agg2_idx<<<AB_AGG, 256>>>(b2);

    // GAT layer 3: transform only marked set (indexed), aggregate only listed nodes
    k_transform_mma_idx<<<dim3(NP / 128, 2), 256, SMEM_MMA>>>(
        (const __half*)p_w3h, a3s, a3d);
    k_gat_agg_list<<<(2 * P * 32 + 255) / 256, 256>>>(b3, bufA, ui, ii, P);

    k_final<<<(1024 * 32 + 255) / 256, 256>>>(bufA, ui, ii, wdnn, out);
}

// round 15
// speedup vs baseline: 1.3544x; 1.0775x over previous
#include <cuda_runtime.h>
#include <cuda_bf16.h>
#include <cuda_fp16.h>
#include <math.h>

#define NN 50000
#define NP 50048          // padded to 128
#define EE 800000
#define ET (EE + NN)      // edges + self loops
#define PIT 264           // smem row pitch (fp16): 33*16B -> LDSM conflict-free

// ---------------- scratch (device globals; no allocation allowed) ----------------
__device__ float d_T2[512 * 16];             // Hd @ Wr
__device__ float d_M[128 * 16];              // Wd @ T2
__device__ int   d_deg[NN];                  // starts 0; scan resets to 0 after use
__device__ int   d_rowoff[NN + 1];
__device__ int   d_cursor[NN];               // gcn_agg resets to 0 after scatter
__device__ float d_dis[NN];
__device__ int   d_csr[ET];
__device__ float d_xw[NN * 16];
__device__ float d_dual[NN * 16];
__device__ float d_h0[NN * 16];
__device__ __half d_h1h[NP * 256];           // fp16 transformed features (agg gather)
__device__ __half d_Ah[NP * 256];            // fp16 activations for layer-2 MMA (pads stay 0)
__device__ float d_bufA[NN * 256];
__device__ float d_sa[NN * 16];
__device__ float d_da[NN * 16];
__device__ __half d_W2h[256 * 256];          // W2^T [n][k] fp16
__device__ __half d_W3h[256 * 256];
__device__ int   d_mark[NN];                 // zero-init; compact resets to 0
__device__ int   d_list[NN];
__device__ int   d_listcnt;

// ================= chain A: degree count =================
__global__ void k_count(const int* __restrict__ dst) {
    int t = blockIdx.x * blockDim.x + threadIdx.x;
    int e0 = t * 4;
    if (e0 + 3 < EE) {
        int4 d4 = *(const int4*)(dst + e0);
        atomicAdd(&d_deg[d4.x], 1);
        atomicAdd(&d_deg[d4.y], 1);
        atomicAdd(&d_deg[d4.z], 1);
        atomicAdd(&d_deg[d4.w], 1);
    } else {
        for (int e = e0; e < EE; e++) atomicAdd(&d_deg[dst[e]], 1);
    }
}

// ================= chain B: prepW | gemmA =================
#define QB_PREPW 512
#define QB_GEMMA 1024
#define QB_TOTAL (QB_PREPW + QB_GEMMA)

__global__ void k_prep(const float* __restrict__ W2, const float* __restrict__ W3,
                       const float* __restrict__ hd, const float* __restrict__ wr) {
    int bid = blockIdx.x, tid = threadIdx.x;
    if (bid < QB_PREPW) {
        int idx = bid * 256 + tid;
        int sel = idx >> 16;
        int r = idx & 65535;
        int n = r >> 8, k = r & 255;
        float w = (sel ? W3 : W2)[k * 256 + n];
        __half h = __float2half_rn(w);
        if (sel) d_W3h[r] = h;
        else     d_W2h[r] = h;
    } else {
        int w = ((bid - QB_PREPW) * 256 + tid) >> 5;
        int lane = tid & 31;
        int i = w >> 4, j = w & 15;
        float a = 0.f;
#pragma unroll
        for (int kk = 0; kk < 16; kk++) {
            int k = lane + kk * 32;
            a += hd[i * 512 + k] * wr[k * 16 + j];
        }
#pragma unroll
        for (int off = 16; off >= 1; off >>= 1)
            a += __shfl_down_sync(0xffffffffu, a, off);
        if (lane == 0) d_T2[w] = a;
    }
}

// ================= chain A: scan (+ fused rsqrt degree, deg reset) =================
__global__ void __launch_bounds__(1024)
k_scan() {
    __shared__ int warp_sums[32];
    int t = threadIdx.x;
    const int S = 49;
    int b0 = t * S;
    int sum = 0;
    for (int i = 0; i < S; i++) {
        int idx = b0 + i;
        if (idx < NN) sum += d_deg[idx] + 1;
    }
    int lane = t & 31, w = t >> 5;
    int v = sum;
#pragma unroll
    for (int off = 1; off < 32; off <<= 1) {
        int u = __shfl_up_sync(0xffffffffu, v, off);
        if (lane >= off) v += u;
    }
    if (lane == 31) warp_sums[w] = v;
    __syncthreads();
    if (w == 0) {
        int ws = warp_sums[lane];
#pragma unroll
        for (int off = 1; off < 32; off <<= 1) {
            int u = __shfl_up_sync(0xffffffffu, ws, off);
            if (lane >= off) ws += u;
        }
        warp_sums[lane] = ws;
    }
    __syncthreads();
    int ex = v - sum + (w > 0 ? warp_sums[w - 1] : 0);
    int run = ex;
    for (int i = 0; i < S; i++) {
        int idx = b0 + i;
        if (idx < NN) {
            int dg = d_deg[idx] + 1;
            d_deg[idx] = 0;
            run += dg;
            d_rowoff[idx + 1] = run;
            d_dis[idx] = rsqrtf((float)dg);
        }
    }
    if (t == 0) d_rowoff[0] = 0;
}

// ================= chain B: gemmB =================
__global__ void __launch_bounds__(1024)
k_gemmB(const float* __restrict__ wd) {
    int w = blockIdx.x * 32 + (threadIdx.x >> 5);
    int lane = threadIdx.x & 31;
    int i = w >> 4, j = w & 15;
    float a = 0.f;
#pragma unroll
    for (int kk = 0; kk < 16; kk++) {
        int k = lane + kk * 32;
        a += wd[i * 512 + k] * d_T2[k * 16 + j];
    }
#pragma unroll
    for (int off = 16; off >= 1; off >>= 1)
        a += __shfl_down_sync(0xffffffffu, a, off);
    if (lane == 0) d_M[w] = a;
}

// ================= chain A: scatter =================
__global__ void k_scatter(const int* __restrict__ ei) {
    int e = blockIdx.x * blockDim.x + threadIdx.x;
    if (e >= ET) return;
    int s, dd;
    if (e < EE) { s = ei[e]; dd = ei[EE + e]; }
    else        { s = dd = e - EE; }
    int p = atomicAdd(&d_cursor[dd], 1);
    d_csr[d_rowoff[dd] + p] = s;
}

// ================= chain B: xw_dual (smem staged) =================
__global__ void __launch_bounds__(256)
k_xw_dual(const float* __restrict__ x, const float* __restrict__ Wg) {
    __shared__ float sx[16][132];
    int tid = threadIdx.x;
    int nb = blockIdx.x * 16;
    const float4* xs = (const float4*)(x + (size_t)nb * 128);
    for (int i = tid; i < 512; i += 256) {
        float4 v = xs[i];
        int r = i >> 5, c = (i & 31) * 4;
        sx[r][c] = v.x; sx[r][c + 1] = v.y; sx[r][c + 2] = v.z; sx[r][c + 3] = v.w;
    }
    __syncthreads();
    int nl = tid >> 4, j = tid & 15;
    float a = 0.f, b = 0.f;
#pragma unroll 4
    for (int k = 0; k < 128; k++) {
        float xv = sx[nl][k];
        a += xv * Wg[k * 16 + j];
        b += xv * d_M[k * 16 + j];
    }
    int n = nb + nl;
    d_xw[n * 16 + j] = a;
    d_dual[n * 16 + j] = b;
}

// ======= merged: GCN aggregation (lean, float4 channels, 4-edge unroll) | mark set =======
#define GB_GCN ((NN * 4 + 255) / 256)

__global__ void k_gcn_agg(const float* __restrict__ bg,
                          const int* __restrict__ ui, const int* __restrict__ ii,
                          int P) {
    int bid = blockIdx.x, tid = threadIdx.x;
    if (bid < GB_GCN) {
        int t = bid * 256 + tid;
        int g = t >> 2, c4 = t & 3;
        if (g >= NN) return;
        int beg = d_rowoff[g], end = d_rowoff[g + 1];
        float4 acc = make_float4(0.f, 0.f, 0.f, 0.f);
        int e = beg;
        for (; e + 3 < end; e += 4) {
            int s0 = d_csr[e], s1 = d_csr[e + 1], s2 = d_csr[e + 2], s3 = d_csr[e + 3];
            float ds0 = d_dis[s0], ds1 = d_dis[s1], ds2 = d_dis[s2], ds3 = d_dis[s3];
            float4 x0 = ((const float4*)(d_xw + s0 * 16))[c4];
            float4 x1 = ((const float4*)(d_xw + s1 * 16))[c4];
            float4 x2 = ((const float4*)(d_xw + s2 * 16))[c4];
            float4 x3 = ((const float4*)(d_xw + s3 * 16))[c4];
            acc.x += ds0 * x0.x + ds1 * x1.x + ds2 * x2.x + ds3 * x3.x;
            acc.y += ds0 * x0.y + ds1 * x1.y + ds2 * x2.y + ds3 * x3.y;
            acc.z += ds0 * x0.z + ds1 * x1.z + ds2 * x2.z + ds3 * x3.z;
            acc.w += ds0 * x0.w + ds1 * x1.w + ds2 * x2.w + ds3 * x3.w;
        }
        for (; e < end; e++) {
            int s = d_csr[e];
            float ds = d_dis[s];
            float4 xw = ((const float4*)(d_xw + s * 16))[c4];
            acc.x += ds * xw.x; acc.y += ds * xw.y;
            acc.z += ds * xw.z; acc.w += ds * xw.w;
        }
        float dg = d_dis[g];
        float4 du = ((const float4*)(d_dual + g * 16))[c4];
        float4 vo;
        vo.x = acc.x * dg + bg[c4 * 4 + 0] + du.x;
        vo.y = acc.y * dg + bg[c4 * 4 + 1] + du.y;
        vo.z = acc.z * dg + bg[c4 * 4 + 2] + du.z;
        vo.w = acc.w * dg + bg[c4 * 4 + 3] + du.w;
        vo.x = vo.x > 0.f ? vo.x : (__expf(vo.x) - 1.f);
        vo.y = vo.y > 0.f ? vo.y : (__expf(vo.y) - 1.f);
        vo.z = vo.z > 0.f ? vo.z : (__expf(vo.z) - 1.f);
        vo.w = vo.w > 0.f ? vo.w : (__expf(vo.w) - 1.f);
        ((float4*)(d_h0 + g * 16))[c4] = vo;
        if (c4 == 0) d_cursor[g] = 0;   // reset for next replay
    } else {
        int i = (bid - GB_GCN) * 256 + tid;
        if (i == 0) d_listcnt = 0;
        if (i < 2 * P) {
            int n = (i < P) ? ui[i] : ii[i - P];
            d_mark[n] = 1;
            int beg = d_rowoff[n], end = d_rowoff[n + 1];
            for (int e = beg; e < end; e++) d_mark[d_csr[e]] = 1;
        }
    }
}

// ---------------- GAT layer-1 transform (FIN=16, FFMA; writes fp16 h1) ----------------
__global__ void __launch_bounds__(128, 8)
k_transform16(const float* __restrict__ hin, const float* __restrict__ W,
              const float* __restrict__ asrc, const float* __restrict__ adst) {
    __shared__ float s[16][16];
    int tid = threadIdx.x;
    int nb = blockIdx.x * 16;
    const float4* hin4 = (const float4*)(hin + nb * 16);
    float4* s4 = (float4*)s;
    for (int t = tid; t < 16 * 16 / 4; t += 128) s4[t] = hin4[t];
    __syncthreads();

    int cg = tid & 63;
    int ng = tid >> 6;
    const float4* W4 = (const float4*)W;
    float4 acc[8];
#pragma unroll
    for (int r = 0; r < 8; r++) acc[r] = make_float4(0.f, 0.f, 0.f, 0.f);

#pragma unroll
    for (int k = 0; k < 16; k++) {
        float4 w = W4[k * 64 + cg];
#pragma unroll
        for (int r = 0; r < 8; r++) {
            float sv = s[ng * 8 + r][k];
            acc[r].x += sv * w.x; acc[r].y += sv * w.y;
            acc[r].z += sv * w.z; acc[r].w += sv * w.w;
        }
    }

    float4 as4 = ((const float4*)asrc)[cg];
    float4 ad4 = ((const float4*)adst)[cg];
#pragma unroll
    for (int r = 0; r < 8; r++) {
        int n = nb + ng * 8 + r;
        if (n >= NN) break;
        __half2 p0 = __floats2half2_rn(acc[r].x, acc[r].y);
        __half2 p1 = __floats2half2_rn(acc[r].z, acc[r].w);
        *(__half2*)&d_h1h[(size_t)n * 256 + cg * 4] = p0;
        *(__half2*)&d_h1h[(size_t)n * 256 + cg * 4 + 2] = p1;
        float vs = acc[r].x * as4.x + acc[r].y * as4.y + acc[r].z * as4.z + acc[r].w * as4.w;
        float vd = acc[r].x * ad4.x + acc[r].y * ad4.y + acc[r].z * ad4.z + acc[r].w * ad4.w;
        vs += __shfl_down_sync(0xffffffffu, vs, 2, 4);
        vs += __shfl_down_sync(0xffffffffu, vs, 1, 4);
        vd += __shfl_down_sync(0xffffffffu, vd, 2, 4);
        vd += __shfl_down_sync(0xffffffffu, vd, 1, 4);
        if ((cg & 3) == 0) {
            int h = cg >> 2;
            d_sa[n * 16 + h] = vs;
            d_da[n * 16 + h] = vd;
        }
    }
}

// ---------------- MMA helpers ----------------
#define MMA_F16(C, A0, A1, A2, A3, B0, B1)                                   \
    asm volatile(                                                            \
        "mma.sync.aligned.m16n8k16.row.col.f32.f16.f16.f32 "                 \
        "{%0,%1,%2,%3}, {%4,%5,%6,%7}, {%8,%9}, {%0,%1,%2,%3};\n"            \
        : "+f"(C[0]), "+f"(C[1]), "+f"(C[2]), "+f"(C[3])                     \
        : "r"(A0), "r"(A1), "r"(A2), "r"(A3), "r"(B0), "r"(B1))

#define LDSM4(R0, R1, R2, R3, ADDR)                                          \
    asm volatile("ldmatrix.sync.aligned.m8n8.x4.shared.b16 {%0,%1,%2,%3}, [%4];" \
        : "=r"(R0), "=r"(R1), "=r"(R2), "=r"(R3) : "r"(ADDR))

#define SMEM_MMA ((128 * PIT + 64 * PIT) * 2)

// mainloop + epilogue over one 64-col B slice; writes rows g0,g1 (-1 = skip)
static __device__ __forceinline__ void mma_core(__half* sA, __half* sB,
                                                int lane, int warp, int n0,
                                                const float* __restrict__ as_,
                                                const float* __restrict__ ad_,
                                                int g0, int g1) {
    float c[8][4];
#pragma unroll
    for (int t = 0; t < 8; t++)
#pragma unroll
        for (int j = 0; j < 4; j++) c[t][j] = 0.f;

    int rA = warp * 16 + (lane & 15);
    int kOff = (lane >> 4) << 3;
    unsigned aB = (unsigned)__cvta_generic_to_shared(sA + rA * PIT + kOff);
    int rB = lane & 15;
    unsigned bB = (unsigned)__cvta_generic_to_shared(sB + rB * PIT + kOff);

#pragma unroll 4
    for (int kc = 0; kc < 16; kc++) {
        unsigned ka = kc * 32;
        unsigned a0, a1, a2, a3;
        LDSM4(a0, a1, a2, a3, aB + ka);
#pragma unroll
        for (int p = 0; p < 4; p++) {
            unsigned boff = (unsigned)(p * 16 * PIT * 2) + ka;
            unsigned b0, b1, b2, b3;
            LDSM4(b0, b1, b2, b3, bB + boff);
            MMA_F16(c[2 * p],     a0, a1, a2, a3, b0, b2);
            MMA_F16(c[2 * p + 1], a0, a1, a2, a3, b1, b3);
        }
    }

    int H0 = n0 >> 4;
    int cbase = (lane & 3) * 2;
    float vs0[4] = {0, 0, 0, 0}, vd0[4] = {0, 0, 0, 0};
    float vs1[4] = {0, 0, 0, 0}, vd1[4] = {0, 0, 0, 0};
#pragma unroll
    for (int t = 0; t < 8; t++) {
        int col = n0 + t * 8 + cbase;
        if (g0 >= 0)
            *(__half2*)&d_h1h[(size_t)g0 * 256 + col] = __floats2half2_rn(c[t][0], c[t][1]);
        if (g1 >= 0)
            *(__half2*)&d_h1h[(size_t)g1 * 256 + col] = __floats2half2_rn(c[t][2], c[t][3]);
        float2 a2 = *(const float2*)&as_[col];
        float2 d2 = *(const float2*)&ad_[col];
        int hh = t >> 1;
        vs0[hh] += c[t][0] * a2.x + c[t][1] * a2.y;
        vd0[hh] += c[t][0] * d2.x + c[t][1] * d2.y;
        vs1[hh] += c[t][2] * a2.x + c[t][3] * a2.y;
        vd1[hh] += c[t][2] * d2.x + c[t][3] * d2.y;
    }
#pragma unroll
    for (int hh = 0; hh < 4; hh++) {
        vs0[hh] += __shfl_down_sync(0xffffffffu, vs0[hh], 2, 4);
        vs0[hh] += __shfl_down_sync(0xffffffffu, vs0[hh], 1, 4);
        vd0[hh] += __shfl_down_sync(0xffffffffu, vd0[hh], 2, 4);
        vd0[hh] += __shfl_down_sync(0xffffffffu, vd0[hh], 1, 4);
        vs1[hh] += __shfl_down_sync(0xffffffffu, vs1[hh], 2, 4);
        vs1[hh] += __shfl_down_sync(0xffffffffu, vs1[hh], 1, 4);
        vd1[hh] += __shfl_down_sync(0xffffffffu, vd1[hh], 2, 4);
        vd1[hh] += __shfl_down_sync(0xffffffffu, vd1[hh], 1, 4);
    }
    if ((lane & 3) == 0) {
        if (g0 >= 0 && g0 < NN) {
#pragma unroll
            for (int hh = 0; hh < 4; hh++) {
                d_sa[g0 * 16 + H0 + hh] = vs0[hh];
                d_da[g0 * 16 + H0 + hh] = vd0[hh];
            }
        }
        if (g1 >= 0 && g1 < NN) {
#pragma unroll
            for (int hh = 0; hh < 4; hh++) {
                d_sa[g1 * 16 + H0 + hh] = vs1[hh];
                d_da[g1 * 16 + H0 + hh] = vd1[hh];
            }
        }
    }
}

static __device__ __forceinline__ void stage_B(__half* sB, const __half* __restrict__ Bh,
                                               int n0, int tid) {
    const uint4* bH = (const uint4*)(Bh + (size_t)n0 * 256);
    for (int i = tid; i < 64 * 32; i += 256) {
        int r = i >> 5, c = i & 31;
        *(uint4*)(sB + r * PIT + c * 8) = bH[r * 32 + c];
    }
}

// layer-2: all rows; 2 sequential 64-col slices per block (A staged once)
__global__ void __launch_bounds__(256, 1)
k_transform_mma(const __half* __restrict__ Bh,
                const float* __restrict__ as_, const float* __restrict__ ad_) {
    extern __shared__ __half sm[];
    __half* sA = sm;
    __half* sB = sA + 128 * PIT;
    int tid = threadIdx.x, lane = tid & 31, warp = tid >> 5;
    int m0 = blockIdx.x * 128;
    {
        const uint4* gA = (const uint4*)(d_Ah + (size_t)m0 * 256);
        for (int i = tid; i < 128 * 32; i += 256) {
            int r = i >> 5, c = i & 31;
            *(uint4*)(sA + r * PIT + c * 8) = gA[r * 32 + c];
        }
    }
    int g0 = m0 + warp * 16 + (lane >> 2);
#pragma unroll
    for (int s = 0; s < 2; s++) {
        int n0 = blockIdx.y * 128 + s * 64;
        stage_B(sB, Bh, n0, tid);
        __syncthreads();
        mma_core(sA, sB, lane, warp, n0, as_, ad_, g0, g0 + 8);
        __syncthreads();
    }
}

// layer-3: only listed rows (gather A by index, scatter outputs)
__global__ void __launch_bounds__(256, 1)
k_transform_mma_idx(const __half* __restrict__ Bh,
                    const float* __restrict__ as_, const float* __restrict__ ad_) {
    extern __shared__ __half sm[];
    __shared__ int snode[128];
    __half* sA = sm;
    __half* sB = sA + 128 * PIT;
    int tid = threadIdx.x, lane = tid & 31, warp = tid >> 5;
    int m0 = blockIdx.x * 128;
    int cnt = d_listcnt;
    if (m0 >= cnt) return;
    for (int i = tid; i < 128; i += 256) {
        int r = m0 + i;
        snode[i] = (r < cnt) ? d_list[r] : -1;
    }
    __syncthreads();
    for (int i = tid; i < 128 * 32; i += 256) {
        int r = i >> 5, c = i & 31;
        int nd = snode[r];
        uint4 v = make_uint4(0, 0, 0, 0);
        if (nd >= 0) v = ((const uint4*)(d_Ah + (size_t)nd * 256))[c];
        *(uint4*)(sA + r * PIT + c * 8) = v;
    }
    int r0 = warp * 16 + (lane >> 2);
#pragma unroll
    for (int s = 0; s < 2; s++) {
        int n0 = blockIdx.y * 128 + s * 64;
        stage_B(sB, Bh, n0, tid);
        __syncthreads();
        mma_core(sA, sB, lane, warp, n0, as_, ad_, snode[r0], snode[r0 + 8]);
        __syncthreads();
    }
}

// ---------------- GAT aggregation body: 4-edge branchless online softmax ----------------
template <bool SPLIT>
static __device__ __forceinline__ void gat_body(int n, int lane,
                                                const float* __restrict__ b,
                                                float* __restrict__ outf) {
    int hd = lane >> 1;
    float da_l = d_da[n * 16 + hd];
    int beg = d_rowoff[n], end = d_rowoff[n + 1];

    float m = -1e30f, z = 0.f;
    float acc[8];
#pragma unroll
    for (int i = 0; i < 8; i++) acc[i] = 0.f;

    int e = beg;
    for (; e + 3 < end; e += 4) {
        int s0 = d_csr[e], s1 = d_csr[e + 1], s2 = d_csr[e + 2], s3 = d_csr[e + 3];
        float l0 = d_sa[s0 * 16 + hd] + da_l;
        float l1 = d_sa[s1 * 16 + hd] + da_l;
        float l2 = d_sa[s2 * 16 + hd] + da_l;
        float l3 = d_sa[s3 * 16 + hd] + da_l;
        uint4 hv0 = *(const uint4*)(d_h1h + (size_t)s0 * 256 + lane * 8);
        uint4 hv1 = *(const uint4*)(d_h1h + (size_t)s1 * 256 + lane * 8);
        uint4 hv2 = *(const uint4*)(d_h1h + (size_t)s2 * 256 + lane * 8);
        uint4 hv3 = *(const uint4*)(d_h1h + (size_t)s3 * 256 + lane * 8);
        l0 = l0 > 0.f ? l0 : 0.2f * l0;
        l1 = l1 > 0.f ? l1 : 0.2f * l1;
        l2 = l2 > 0.f ? l2 : 0.2f * l2;
        l3 = l3 > 0.f ? l3 : 0.2f * l3;
        float nm = fmaxf(fmaxf(m, fmaxf(l0, l1)), fmaxf(l2, l3));
        float sc = __expf(m - nm);
        float e0 = __expf(l0 - nm), e1 = __expf(l1 - nm);
        float e2 = __expf(l2 - nm), e3 = __expf(l3 - nm);
        m = nm;
        z = z * sc + (e0 + e1) + (e2 + e3);
        float2 f0 = __half22float2(*(__half2*)&hv0.x), f1 = __half22float2(*(__half2*)&hv0.y);
        float2 f2 = __half22float2(*(__half2*)&hv0.z), f3 = __half22float2(*(__half2*)&hv0.w);
        float2 g0 = __half22float2(*(__half2*)&hv1.x), g1 = __half22float2(*(__half2*)&hv1.y);
        float2 g2 = __half22float2(*(__half2*)&hv1.z), g3 = __half22float2(*(__half2*)&hv1.w);
        float2 p0 = __half22float2(*(__half2*)&hv2.x), p1 = __half22float2(*(__half2*)&hv2.y);
        float2 p2 = __half22float2(*(__half2*)&hv2.z), p3 = __half22float2(*(__half2*)&hv2.w);
        float2 q0 = __half22float2(*(__half2*)&hv3.x), q1 = __half22float2(*(__half2*)&hv3.y);
        float2 q2 = __half22float2(*(__half2*)&hv3.z), q3 = __half22float2(*(__half2*)&hv3.w);
        acc[0] = acc[0] * sc + (e0 * f0.x + e1 * g0.x) + (e2 * p0.x + e3 * q0.x);
        acc[1] = acc[1] * sc + (e0 * f0.y + e1 * g0.y) + (e2 * p0.y + e3 * q0.y);
        acc[2] = acc[2] * sc + (e0 * f1.x + e1 * g1.x) + (e2 * p1.x + e3 * q1.x);
        acc[3] = acc[3] * sc + (e0 * f1.y + e1 * g1.y) + (e2 * p1.y + e3 * q1.y);
        acc[4] = acc[4] * sc + (e0 * f2.x + e1 * g2.x) + (e2 * p2.x + e3 * q2.x);
        acc[5] = acc[5] * sc + (e0 * f2.y + e1 * g2.y) + (e2 * p2.y + e3 * q2.y);
        acc[6] = acc[6] * sc + (e0 * f3.x + e1 * g3.x) + (e2 * p3.x + e3 * q3.x);
        acc[7] = acc[7] * sc + (e0 * f3.y + e1 * g3.y) + (e2 * p3.y + e3 * q3.y);
    }
    for (; e < end; e++) {
        int s0 = d_csr[e];
        float l0 = d_sa[s0 * 16 + hd] + da_l;
        uint4 hv0 = *(const uint4*)(d_h1h + (size_t)s0 * 256 + lane * 8);
        l0 = l0 > 0.f ? l0 : 0.2f * l0;
        float nm = fmaxf(m, l0);
        float sc = __expf(m - nm);
        float e0 = __expf(l0 - nm);
        m = nm;
        z = z * sc + e0;
        float2 f0 = __half22float2(*(__half2*)&hv0.x), f1 = __half22float2(*(__half2*)&hv0.y);
        float2 f2 = __half22float2(*(__half2*)&hv0.z), f3 = __half22float2(*(__half2*)&hv0.w);
        acc[0] = acc[0] * sc + e0 * f0.x;
        acc[1] = acc[1] * sc + e0 * f0.y;
        acc[2] = acc[2] * sc + e0 * f1.x;
        acc[3] = acc[3] * sc + e0 * f1.y;
        acc[4] = acc[4] * sc + e0 * f2.x;
        acc[5] = acc[5] * sc + e0 * f2.y;
        acc[6] = acc[6] * sc + e0 * f3.x;
        acc[7] = acc[7] * sc + e0 * f3.y;
    }

    float invz = 1.f / (z + 1e-16f);
    float vo[8];
#pragma unroll
    for (int i = 0; i < 8; i++) {
        float v = acc[i] * invz + b[lane * 8 + i];
        vo[i] = v > 0.f ? v : (__expf(v) - 1.f);
    }
    if (SPLIT) {
        __half2 h0 = __floats2half2_rn(vo[0], vo[1]);
        __half2 h1 = __floats2half2_rn(vo[2], vo[3]);
        __half2 h2 = __floats2half2_rn(vo[4], vo[5]);
        __half2 h3 = __floats2half2_rn(vo[6], vo[7]);
        uint4 pk;
        pk.x = *(unsigned*)&h0; pk.y = *(unsigned*)&h1;
        pk.z = *(unsigned*)&h2; pk.w = *(unsigned*)&h3;
        *(uint4*)&d_Ah[(size_t)n * 256 + lane * 8] = pk;
    } else {
        *(float4*)&outf[(size_t)n * 256 + lane * 8] = make_float4(vo[0], vo[1], vo[2], vo[3]);
        *(float4*)&outf[(size_t)n * 256 + lane * 8 + 4] = make_float4(vo[4], vo[5], vo[6], vo[7]);
    }
}

// layer-1 agg (all nodes) | compact tail blocks
#define AB_AGG ((NN * 32) / 256)
#define AB_CMP ((NN + 255) / 256)

__global__ void k_agg1(const float* __restrict__ b) {
    int bid = blockIdx.x;
    if (bid < AB_AGG) {
        int n = (bid * 256 + threadIdx.x) >> 5;
        if (n >= NN) return;
        gat_body<true>(n, threadIdx.x & 31, b, nullptr);
    } else {
        int i = (bid - AB_AGG) * 256 + threadIdx.x;
        if (i < NN && d_mark[i]) {
            int pos = atomicAdd(&d_listcnt, 1);
            d_list[pos] = i;
            d_mark[i] = 0;
        }
    }
}

// layer-2 agg: only listed nodes
__global__ void k_agg2_idx(const float* __restrict__ b) {
    int i = (blockIdx.x * blockDim.x + threadIdx.x) >> 5;
    if (i >= d_listcnt) return;
    gat_body<true>(d_list[i], threadIdx.x & 31, b, nullptr);
}

// layer-3: aggregate ONLY the user/item nodes
__global__ void k_gat_agg_list(const float* __restrict__ b, float* __restrict__ outf,
                               const int* __restrict__ ui, const int* __restrict__ ii,
                               int P) {
    int i = (blockIdx.x * blockDim.x + threadIdx.x) >> 5;
    if (i >= 2 * P) return;
    int n = (i < P) ? ui[i] : ii[i - P];
    gat_body<false>(n, threadIdx.x & 31, b, outf);
}

// ---------------- final ----------------
__global__ void k_final(const float* __restrict__ h, const int* __restrict__ ui,
                        const int* __restrict__ ii, const float* __restrict__ Wd,
                        float* __restrict__ out) {
    int p = (blockIdx.x * blockDim.x + threadIdx.x) >> 5;
    if (p >= 1024) return;
    int lane = threadIdx.x & 31;
    int u = ui[p], it = ii[p];
    float a0 = 0.f, a1 = 0.f;
    for (int k = lane; k < 256; k += 32) {
        float v = h[u * 256 + k];
        a0 += v * Wd[k * 2 + 0];
        a1 += v * Wd[k * 2 + 1];
        float w = h[it * 256 + k];
        a0 += w * Wd[(256 + k) * 2 + 0];
        a1 += w * Wd[(256 + k) * 2 + 1];
    }
#pragma unroll
    for (int off = 16; off >= 1; off >>= 1) {
        a0 += __shfl_down_sync(0xffffffffu, a0, off);
        a1 += __shfl_down_sync(0xffffffffu, a1, off);
    }
    if (lane == 0) {
        float mx = fmaxf(a0, a1);
        float lse = mx + __logf(__expf(a0 - mx) + __expf(a1 - mx));
        out[p * 2 + 0] = a0 - lse;
        out[p * 2 + 1] = a1 - lse;
    }
}

// ---------------- launcher ----------------
extern "C" void kernel_launch(void* const* d_in, const int* in_sizes, int n_in,
                              void* d_out, int out_size) {
    const float* x    = (const float*)d_in[0];
    const int*   ei   = (const int*)d_in[1];
    const float* Hd   = (const float*)d_in[2];
    const int*   ui   = (const int*)d_in[3];
    const int*   ii   = (const int*)d_in[4];
    const float* Wg   = (const float*)d_in[5];
    const float* bg   = (const float*)d_in[6];
    const float* W1   = (const float*)d_in[7];
    const float* a1s  = (const float*)d_in[8];
    const float* a1d  = (const float*)d_in[9];
    const float* b1   = (const float*)d_in[10];
    const float* W2   = (const float*)d_in[11];
    const float* a2s  = (const float*)d_in[12];
    const float* a2d  = (const float*)d_in[13];
    const float* b2   = (const float*)d_in[14];
    const float* W3   = (const float*)d_in[15];
    const float* a3s  = (const float*)d_in[16];
    const float* a3d  = (const float*)d_in[17];
    const float* b3   = (const float*)d_in[18];
    const float* wd   = (const float*)d_in[19];
    const float* wr   = (const float*)d_in[20];
    const float* wdnn = (const float*)d_in[21];
    float* out = (float*)d_out;

    int P = in_sizes[3];   // number of user/item pairs

    void *p_h0, *p_bufA, *p_w2h, *p_w3h;
    cudaGetSymbolAddress(&p_h0, d_h0);
    cudaGetSymbolAddress(&p_bufA, d_bufA);
    cudaGetSymbolAddress(&p_w2h, d_W2h);
    cudaGetSymbolAddress(&p_w3h, d_W3h);
    float* h0   = (float*)p_h0;
    float* bufA = (float*)p_bufA;

    cudaFuncSetAttribute(k_transform_mma,
                         cudaFuncAttributeMaxDynamicSharedMemorySize, SMEM_MMA);
    cudaFuncSetAttribute(k_transform_mma_idx,
                         cudaFuncAttributeMaxDynamicSharedMemorySize, SMEM_MMA);

    // fork: chain B (dense prep) on sB, chain A (graph build) on the default stream
    cudaStream_t sB;
    cudaStreamCreateWithFlags(&sB, cudaStreamNonBlocking);
    cudaEvent_t evFork, evJoin;
    cudaEventCreateWithFlags(&evFork, cudaEventDisableTiming);
    cudaEventCreateWithFlags(&evJoin, cudaEventDisableTiming);

    cudaEventRecord(evFork, 0);
    cudaStreamWaitEvent(sB, evFork, 0);

    // chain B: prepW | gemmA -> gemmB -> xw_dual
    k_prep<<<QB_TOTAL, 256, 0, sB>>>(W2, W3, Hd, wr);
    k_gemmB<<<64, 1024, 0, sB>>>(wd);
    k_xw_dual<<<NN / 16, 256, 0, sB>>>(x, Wg);
    cudaEventRecord(evJoin, sB);

    // chain A: count -> scan -> scatter
    k_count<<<(EE / 4 + 255) / 256, 256>>>(ei + EE);
    k_scan<<<1, 1024>>>();
    k_scatter<<<(ET + 255) / 256, 256>>>(ei);

    // join
    cudaStreamWaitEvent(0, evJoin, 0);

    k_gcn_agg<<<GB_GCN + (2 * P + 255) / 256, 256>>>(bg, ui, ii, P);

    // GAT layer 1 (all nodes) + compact tail
    k_transform16<<<NN / 16, 128>>>(h0, W1, a1s, a1d);
    k_agg1<<<AB_AGG + AB_CMP, 256>>>(b1);

    // GAT layer 2: transform all nodes (A staged once per block, 2 B slices)
    k_transform_mma<<<dim3(NP / 128, 2), 256, SMEM_MMA>>>(
        (const __half*)p_w2h, a2s, a2d);
    k_agg2_idx<<<AB_AGG, 256>>>(b2);

    // GAT layer 3: transform only marked set (indexed), aggregate only listed nodes
    k_transform_mma_idx<<<dim3(NP / 128, 2), 256, SMEM_MMA>>>(
        (const __half*)p_w3h, a3s, a3d);
    k_gat_agg_list<<<(2 * P * 32 + 255) / 256, 256>>>(b3, bufA, ui, ii, P);

    k_final<<<(1024 * 32 + 255) / 256, 256>>>(bufA, ui, ii, wdnn, out);

    cudaEventDestroy(evFork);
    cudaEventDestroy(evJoin);
    cudaStreamDestroy(sB);
}

// round 16
// speedup vs baseline: 1.3631x; 1.0064x over previous
#include <cuda_runtime.h>
#include <cuda_bf16.h>
#include <cuda_fp16.h>
#include <math.h>

#define NN 50000
#define NP 50048          // padded to 128
#define EE 800000
#define ET (EE + NN)      // edges + self loops
#define PIT 264           // smem row pitch (fp16): 33*16B -> LDSM conflict-free

// ---------------- scratch (device globals; no allocation allowed) ----------------
__device__ float d_T2[512 * 16];             // Hd @ Wr
__device__ float d_M[128 * 16];              // Wd @ T2
__device__ int   d_deg[NN];                  // starts 0; scan resets to 0 after use
__device__ int   d_rowoff[NN + 1];
__device__ int   d_cursor[NN];               // gcn_agg resets to 0 after scatter
__device__ float d_dis[NN];
__device__ int   d_csr[ET];
__device__ float d_xw[NN * 16];
__device__ float d_dual[NN * 16];
__device__ float d_h0[NN * 16];
__device__ __half d_h1h[NP * 256];           // fp16 transformed features (agg gather)
__device__ __half d_Ah[NP * 256];            // fp16 activations for layer-2 MMA (pads stay 0)
__device__ float d_bufA[NN * 256];
__device__ float d_sa[NN * 16];
__device__ float d_da[NN * 16];
__device__ __half d_W2h[256 * 256];          // W2^T [n][k] fp16
__device__ __half d_W3h[256 * 256];
__device__ int   d_mark[NN];                 // zero-init; compact resets to 0
__device__ int   d_list[NN];
__device__ int   d_listcnt;

// ================= chain A: degree count (8 edges/thread) =================
__global__ void k_count(const int* __restrict__ dst) {
    int t = blockIdx.x * blockDim.x + threadIdx.x;
    int e0 = t * 8;
    if (e0 + 7 < EE) {
        int4 a = *(const int4*)(dst + e0);
        int4 b = *(const int4*)(dst + e0 + 4);
        atomicAdd(&d_deg[a.x], 1);
        atomicAdd(&d_deg[a.y], 1);
        atomicAdd(&d_deg[a.z], 1);
        atomicAdd(&d_deg[a.w], 1);
        atomicAdd(&d_deg[b.x], 1);
        atomicAdd(&d_deg[b.y], 1);
        atomicAdd(&d_deg[b.z], 1);
        atomicAdd(&d_deg[b.w], 1);
    } else {
        for (int e = e0; e < EE; e++) atomicAdd(&d_deg[dst[e]], 1);
    }
}

// ================= chain B: prepW | gemmA =================
#define QB_PREPW 512
#define QB_GEMMA 1024
#define QB_TOTAL (QB_PREPW + QB_GEMMA)

__global__ void k_prep(const float* __restrict__ W2, const float* __restrict__ W3,
                       const float* __restrict__ hd, const float* __restrict__ wr) {
    int bid = blockIdx.x, tid = threadIdx.x;
    if (bid < QB_PREPW) {
        int idx = bid * 256 + tid;
        int sel = idx >> 16;
        int r = idx & 65535;
        int n = r >> 8, k = r & 255;
        float w = (sel ? W3 : W2)[k * 256 + n];
        __half h = __float2half_rn(w);
        if (sel) d_W3h[r] = h;
        else     d_W2h[r] = h;
    } else {
        int w = ((bid - QB_PREPW) * 256 + tid) >> 5;
        int lane = tid & 31;
        int i = w >> 4, j = w & 15;
        float a = 0.f;
#pragma unroll
        for (int kk = 0; kk < 16; kk++) {
            int k = lane + kk * 32;
            a += hd[i * 512 + k] * wr[k * 16 + j];
        }
#pragma unroll
        for (int off = 16; off >= 1; off >>= 1)
            a += __shfl_down_sync(0xffffffffu, a, off);
        if (lane == 0) d_T2[w] = a;
    }
}

// ================= chain A: scan (+ fused rsqrt degree, deg reset) =================
__global__ void __launch_bounds__(1024)
k_scan() {
    __shared__ int warp_sums[32];
    int t = threadIdx.x;
    const int S = 49;
    int b0 = t * S;
    int sum = 0;
    for (int i = 0; i < S; i++) {
        int idx = b0 + i;
        if (idx < NN) sum += d_deg[idx] + 1;
    }
    int lane = t & 31, w = t >> 5;
    int v = sum;
#pragma unroll
    for (int off = 1; off < 32; off <<= 1) {
        int u = __shfl_up_sync(0xffffffffu, v, off);
        if (lane >= off) v += u;
    }
    if (lane == 31) warp_sums[w] = v;
    __syncthreads();
    if (w == 0) {
        int ws = warp_sums[lane];
#pragma unroll
        for (int off = 1; off < 32; off <<= 1) {
            int u = __shfl_up_sync(0xffffffffu, ws, off);
            if (lane >= off) ws += u;
        }
        warp_sums[lane] = ws;
    }
    __syncthreads();
    int ex = v - sum + (w > 0 ? warp_sums[w - 1] : 0);
    int run = ex;
    for (int i = 0; i < S; i++) {
        int idx = b0 + i;
        if (idx < NN) {
            int dg = d_deg[idx] + 1;
            d_deg[idx] = 0;
            run += dg;
            d_rowoff[idx + 1] = run;
            d_dis[idx] = rsqrtf((float)dg);
        }
    }
    if (t == 0) d_rowoff[0] = 0;
}

// ================= chain B: gemmB =================
__global__ void __launch_bounds__(1024)
k_gemmB(const float* __restrict__ wd) {
    int w = blockIdx.x * 32 + (threadIdx.x >> 5);
    int lane = threadIdx.x & 31;
    int i = w >> 4, j = w & 15;
    float a = 0.f;
#pragma unroll
    for (int kk = 0; kk < 16; kk++) {
        int k = lane + kk * 32;
        a += wd[i * 512 + k] * d_T2[k * 16 + j];
    }
#pragma unroll
    for (int off = 16; off >= 1; off >>= 1)
        a += __shfl_down_sync(0xffffffffu, a, off);
    if (lane == 0) d_M[w] = a;
}

// ================= chain A: scatter =================
__global__ void k_scatter(const int* __restrict__ ei) {
    int e = blockIdx.x * blockDim.x + threadIdx.x;
    if (e >= ET) return;
    int s, dd;
    if (e < EE) { s = ei[e]; dd = ei[EE + e]; }
    else        { s = dd = e - EE; }
    int p = atomicAdd(&d_cursor[dd], 1);
    d_csr[d_rowoff[dd] + p] = s;
}

// ================= chain B: xw_dual (smem staged) =================
__global__ void __launch_bounds__(256)
k_xw_dual(const float* __restrict__ x, const float* __restrict__ Wg) {
    __shared__ float sx[16][132];
    int tid = threadIdx.x;
    int nb = blockIdx.x * 16;
    const float4* xs = (const float4*)(x + (size_t)nb * 128);
    for (int i = tid; i < 512; i += 256) {
        float4 v = xs[i];
        int r = i >> 5, c = (i & 31) * 4;
        sx[r][c] = v.x; sx[r][c + 1] = v.y; sx[r][c + 2] = v.z; sx[r][c + 3] = v.w;
    }
    __syncthreads();
    int nl = tid >> 4, j = tid & 15;
    float a = 0.f, b = 0.f;
#pragma unroll 4
    for (int k = 0; k < 128; k++) {
        float xv = sx[nl][k];
        a += xv * Wg[k * 16 + j];
        b += xv * d_M[k * 16 + j];
    }
    int n = nb + nl;
    d_xw[n * 16 + j] = a;
    d_dual[n * 16 + j] = b;
}

// ======= merged: GCN aggregation (index-prefetch pipeline) | mark set =======
#define GB_GCN ((NN * 4 + 255) / 256)

__global__ void k_gcn_agg(const float* __restrict__ bg,
                          const int* __restrict__ ui, const int* __restrict__ ii,
                          int P) {
    int bid = blockIdx.x, tid = threadIdx.x;
    if (bid < GB_GCN) {
        int t = bid * 256 + tid;
        int g = t >> 2, c4 = t & 3;
        if (g >= NN) return;
        int beg = d_rowoff[g], end = d_rowoff[g + 1];
        float4 acc = make_float4(0.f, 0.f, 0.f, 0.f);
        int e = beg;
        if (e + 3 < end) {
            int s0 = d_csr[e], s1 = d_csr[e + 1], s2 = d_csr[e + 2], s3 = d_csr[e + 3];
            while (true) {
                int en = e + 4;
                bool more = (en + 3 < end);
                int t0, t1, t2, t3;
                if (more) { t0 = d_csr[en]; t1 = d_csr[en + 1]; t2 = d_csr[en + 2]; t3 = d_csr[en + 3]; }
                float ds0 = d_dis[s0], ds1 = d_dis[s1], ds2 = d_dis[s2], ds3 = d_dis[s3];
                float4 x0 = ((const float4*)(d_xw + s0 * 16))[c4];
                float4 x1 = ((const float4*)(d_xw + s1 * 16))[c4];
                float4 x2 = ((const float4*)(d_xw + s2 * 16))[c4];
                float4 x3 = ((const float4*)(d_xw + s3 * 16))[c4];
                acc.x += ds0 * x0.x + ds1 * x1.x + ds2 * x2.x + ds3 * x3.x;
                acc.y += ds0 * x0.y + ds1 * x1.y + ds2 * x2.y + ds3 * x3.y;
                acc.z += ds0 * x0.z + ds1 * x1.z + ds2 * x2.z + ds3 * x3.z;
                acc.w += ds0 * x0.w + ds1 * x1.w + ds2 * x2.w + ds3 * x3.w;
                e = en;
                if (!more) break;
                s0 = t0; s1 = t1; s2 = t2; s3 = t3;
            }
        }
        for (; e < end; e++) {
            int s = d_csr[e];
            float ds = d_dis[s];
            float4 xw = ((const float4*)(d_xw + s * 16))[c4];
            acc.x += ds * xw.x; acc.y += ds * xw.y;
            acc.z += ds * xw.z; acc.w += ds * xw.w;
        }
        float dg = d_dis[g];
        float4 du = ((const float4*)(d_dual + g * 16))[c4];
        float4 vo;
        vo.x = acc.x * dg + bg[c4 * 4 + 0] + du.x;
        vo.y = acc.y * dg + bg[c4 * 4 + 1] + du.y;
        vo.z = acc.z * dg + bg[c4 * 4 + 2] + du.z;
        vo.w = acc.w * dg + bg[c4 * 4 + 3] + du.w;
        vo.x = vo.x > 0.f ? vo.x : (__expf(vo.x) - 1.f);
        vo.y = vo.y > 0.f ? vo.y : (__expf(vo.y) - 1.f);
        vo.z = vo.z > 0.f ? vo.z : (__expf(vo.z) - 1.f);
        vo.w = vo.w > 0.f ? vo.w : (__expf(vo.w) - 1.f);
        ((float4*)(d_h0 + g * 16))[c4] = vo;
        if (c4 == 0) d_cursor[g] = 0;   // reset for next replay
    } else {
        int i = (bid - GB_GCN) * 256 + tid;
        if (i == 0) d_listcnt = 0;
        if (i < 2 * P) {
            int n = (i < P) ? ui[i] : ii[i - P];
            d_mark[n] = 1;
            int beg = d_rowoff[n], end = d_rowoff[n + 1];
            for (int e = beg; e < end; e++) d_mark[d_csr[e]] = 1;
        }
    }
}

// ---------------- GAT layer-1 transform (FIN=16, FFMA; writes fp16 h1) ----------------
__global__ void __launch_bounds__(128, 8)
k_transform16(const float* __restrict__ hin, const float* __restrict__ W,
              const float* __restrict__ asrc, const float* __restrict__ adst) {
    __shared__ float s[16][16];
    int tid = threadIdx.x;
    int nb = blockIdx.x * 16;
    const float4* hin4 = (const float4*)(hin + nb * 16);
    float4* s4 = (float4*)s;
    for (int t = tid; t < 16 * 16 / 4; t += 128) s4[t] = hin4[t];
    __syncthreads();

    int cg = tid & 63;
    int ng = tid >> 6;
    const float4* W4 = (const float4*)W;
    float4 acc[8];
#pragma unroll
    for (int r = 0; r < 8; r++) acc[r] = make_float4(0.f, 0.f, 0.f, 0.f);

#pragma unroll
    for (int k = 0; k < 16; k++) {
        float4 w = W4[k * 64 + cg];
#pragma unroll
        for (int r = 0; r < 8; r++) {
            float sv = s[ng * 8 + r][k];
            acc[r].x += sv * w.x; acc[r].y += sv * w.y;
            acc[r].z += sv * w.z; acc[r].w += sv * w.w;
        }
    }

    float4 as4 = ((const float4*)asrc)[cg];
    float4 ad4 = ((const float4*)adst)[cg];
#pragma unroll
    for (int r = 0; r < 8; r++) {
        int n = nb + ng * 8 + r;
        if (n >= NN) break;
        __half2 p0 = __floats2half2_rn(acc[r].x, acc[r].y);
        __half2 p1 = __floats2half2_rn(acc[r].z, acc[r].w);
        *(__half2*)&d_h1h[(size_t)n * 256 + cg * 4] = p0;
        *(__half2*)&d_h1h[(size_t)n * 256 + cg * 4 + 2] = p1;
        float vs = acc[r].x * as4.x + acc[r].y * as4.y + acc[r].z * as4.z + acc[r].w * as4.w;
        float vd = acc[r].x * ad4.x + acc[r].y * ad4.y + acc[r].z * ad4.z + acc[r].w * ad4.w;
        vs += __shfl_down_sync(0xffffffffu, vs, 2, 4);
        vs += __shfl_down_sync(0xffffffffu, vs, 1, 4);
        vd += __shfl_down_sync(0xffffffffu, vd, 2, 4);
        vd += __shfl_down_sync(0xffffffffu, vd, 1, 4);
        if ((cg & 3) == 0) {
            int h = cg >> 2;
            d_sa[n * 16 + h] = vs;
            d_da[n * 16 + h] = vd;
        }
    }
}

// ---------------- MMA helpers ----------------
#define MMA_F16(C, A0, A1, A2, A3, B0, B1)                                   \
    asm volatile(                                                            \
        "mma.sync.aligned.m16n8k16.row.col.f32.f16.f16.f32 "                 \
        "{%0,%1,%2,%3}, {%4,%5,%6,%7}, {%8,%9}, {%0,%1,%2,%3};\n"            \
        : "+f"(C[0]), "+f"(C[1]), "+f"(C[2]), "+f"(C[3])                     \
        : "r"(A0), "r"(A1), "r"(A2), "r"(A3), "r"(B0), "r"(B1))

#define LDSM4(R0, R1, R2, R3, ADDR)                                          \
    asm volatile("ldmatrix.sync.aligned.m8n8.x4.shared.b16 {%0,%1,%2,%3}, [%4];" \
        : "=r"(R0), "=r"(R1), "=r"(R2), "=r"(R3) : "r"(ADDR))

#define SMEM_MMA ((128 * PIT + 64 * PIT) * 2)

// mainloop + epilogue over one 64-col B slice; writes rows g0,g1 (-1 = skip)
static __device__ __forceinline__ void mma_core(__half* sA, __half* sB,
                                                int lane, int warp, int n0,
                                                const float* __restrict__ as_,
                                                const float* __restrict__ ad_,
                                                int g0, int g1) {
    float c[8][4];
#pragma unroll
    for (int t = 0; t < 8; t++)
#pragma unroll
        for (int j = 0; j < 4; j++) c[t][j] = 0.f;

    int rA = warp * 16 + (lane & 15);
    int kOff = (lane >> 4) << 3;
    unsigned aB = (unsigned)__cvta_generic_to_shared(sA + rA * PIT + kOff);
    int rB = lane & 15;
    unsigned bB = (unsigned)__cvta_generic_to_shared(sB + rB * PIT + kOff);

#pragma unroll 4
    for (int kc = 0; kc < 16; kc++) {
        unsigned ka = kc * 32;
        unsigned a0, a1, a2, a3;
        LDSM4(a0, a1, a2, a3, aB + ka);
#pragma unroll
        for (int p = 0; p < 4; p++) {
            unsigned boff = (unsigned)(p * 16 * PIT * 2) + ka;
            unsigned b0, b1, b2, b3;
            LDSM4(b0, b1, b2, b3, bB + boff);
            MMA_F16(c[2 * p],     a0, a1, a2, a3, b0, b2);
            MMA_F16(c[2 * p + 1], a0, a1, a2, a3, b1, b3);
        }
    }

    int H0 = n0 >> 4;
    int cbase = (lane & 3) * 2;
    float vs0[4] = {0, 0, 0, 0}, vd0[4] = {0, 0, 0, 0};
    float vs1[4] = {0, 0, 0, 0}, vd1[4] = {0, 0, 0, 0};
#pragma unroll
    for (int t = 0; t < 8; t++) {
        int col = n0 + t * 8 + cbase;
        if (g0 >= 0)
            *(__half2*)&d_h1h[(size_t)g0 * 256 + col] = __floats2half2_rn(c[t][0], c[t][1]);
        if (g1 >= 0)
            *(__half2*)&d_h1h[(size_t)g1 * 256 + col] = __floats2half2_rn(c[t][2], c[t][3]);
        float2 a2 = *(const float2*)&as_[col];
        float2 d2 = *(const float2*)&ad_[col];
        int hh = t >> 1;
        vs0[hh] += c[t][0] * a2.x + c[t][1] * a2.y;
        vd0[hh] += c[t][0] * d2.x + c[t][1] * d2.y;
        vs1[hh] += c[t][2] * a2.x + c[t][3] * a2.y;
        vd1[hh] += c[t][2] * d2.x + c[t][3] * d2.y;
    }
#pragma unroll
    for (int hh = 0; hh < 4; hh++) {
        vs0[hh] += __shfl_down_sync(0xffffffffu, vs0[hh], 2, 4);
        vs0[hh] += __shfl_down_sync(0xffffffffu, vs0[hh], 1, 4);
        vd0[hh] += __shfl_down_sync(0xffffffffu, vd0[hh], 2, 4);
        vd0[hh] += __shfl_down_sync(0xffffffffu, vd0[hh], 1, 4);
        vs1[hh] += __shfl_down_sync(0xffffffffu, vs1[hh], 2, 4);
        vs1[hh] += __shfl_down_sync(0xffffffffu, vs1[hh], 1, 4);
        vd1[hh] += __shfl_down_sync(0xffffffffu, vd1[hh], 2, 4);
        vd1[hh] += __shfl_down_sync(0xffffffffu, vd1[hh], 1, 4);
    }
    if ((lane & 3) == 0) {
        if (g0 >= 0 && g0 < NN) {
#pragma unroll
            for (int hh = 0; hh < 4; hh++) {
                d_sa[g0 * 16 + H0 + hh] = vs0[hh];
                d_da[g0 * 16 + H0 + hh] = vd0[hh];
            }
        }
        if (g1 >= 0 && g1 < NN) {
#pragma unroll
            for (int hh = 0; hh < 4; hh++) {
                d_sa[g1 * 16 + H0 + hh] = vs1[hh];
                d_da[g1 * 16 + H0 + hh] = vd1[hh];
            }
        }
    }
}

static __device__ __forceinline__ void stage_B(__half* sB, const __half* __restrict__ Bh,
                                               int n0, int tid) {
    const uint4* bH = (const uint4*)(Bh + (size_t)n0 * 256);
    for (int i = tid; i < 64 * 32; i += 256) {
        int r = i >> 5, c = i & 31;
        *(uint4*)(sB + r * PIT + c * 8) = bH[r * 32 + c];
    }
}

// layer-2: all rows; 2 sequential 64-col slices per block (A staged once)
__global__ void __launch_bounds__(256, 1)
k_transform_mma(const __half* __restrict__ Bh,
                const float* __restrict__ as_, const float* __restrict__ ad_) {
    extern __shared__ __half sm[];
    __half* sA = sm;
    __half* sB = sA + 128 * PIT;
    int tid = threadIdx.x, lane = tid & 31, warp = tid >> 5;
    int m0 = blockIdx.x * 128;
    {
        const uint4* gA = (const uint4*)(d_Ah + (size_t)m0 * 256);
        for (int i = tid; i < 128 * 32; i += 256) {
            int r = i >> 5, c = i & 31;
            *(uint4*)(sA + r * PIT + c * 8) = gA[r * 32 + c];
        }
    }
    int g0 = m0 + warp * 16 + (lane >> 2);
#pragma unroll
    for (int s = 0; s < 2; s++) {
        int n0 = blockIdx.y * 128 + s * 64;
        stage_B(sB, Bh, n0, tid);
        __syncthreads();
        mma_core(sA, sB, lane, warp, n0, as_, ad_, g0, g0 + 8);
        __syncthreads();
    }
}

// layer-3: only listed rows (gather A by index, scatter outputs)
__global__ void __launch_bounds__(256, 1)
k_transform_mma_idx(const __half* __restrict__ Bh,
                    const float* __restrict__ as_, const float* __restrict__ ad_) {
    extern __shared__ __half sm[];
    __shared__ int snode[128];
    __half* sA = sm;
    __half* sB = sA + 128 * PIT;
    int tid = threadIdx.x, lane = tid & 31, warp = tid >> 5;
    int m0 = blockIdx.x * 128;
    int cnt = d_listcnt;
    if (m0 >= cnt) return;
    for (int i = tid; i < 128; i += 256) {
        int r = m0 + i;
        snode[i] = (r < cnt) ? d_list[r] : -1;
    }
    __syncthreads();
    for (int i = tid; i < 128 * 32; i += 256) {
        int r = i >> 5, c = i & 31;
        int nd = snode[r];
        uint4 v = make_uint4(0, 0, 0, 0);
        if (nd >= 0) v = ((const uint4*)(d_Ah + (size_t)nd * 256))[c];
        *(uint4*)(sA + r * PIT + c * 8) = v;
    }
    int r0 = warp * 16 + (lane >> 2);
#pragma unroll
    for (int s = 0; s < 2; s++) {
        int n0 = blockIdx.y * 128 + s * 64;
        stage_B(sB, Bh, n0, tid);
        __syncthreads();
        mma_core(sA, sB, lane, warp, n0, as_, ad_, snode[r0], snode[r0 + 8]);
        __syncthreads();
    }
}

// ---------------- GAT aggregation body: prefetched 4-edge online softmax ----------------
template <bool SPLIT>
static __device__ __forceinline__ void gat_body(int n, int lane,
                                                const float* __restrict__ b,
                                                float* __restrict__ outf) {
    int hd = lane >> 1;
    float da_l = d_da[n * 16 + hd];
    int beg = d_rowoff[n], end = d_rowoff[n + 1];

    float m = -1e30f, z = 0.f;
    float acc[8];
#pragma unroll
    for (int i = 0; i < 8; i++) acc[i] = 0.f;

    int e = beg;
    if (e + 3 < end) {
        int s0 = d_csr[e], s1 = d_csr[e + 1], s2 = d_csr[e + 2], s3 = d_csr[e + 3];
        while (true) {
            int en = e + 4;
            bool more = (en + 3 < end);
            int t0, t1, t2, t3;
            if (more) { t0 = d_csr[en]; t1 = d_csr[en + 1]; t2 = d_csr[en + 2]; t3 = d_csr[en + 3]; }
            float l0 = d_sa[s0 * 16 + hd] + da_l;
            float l1 = d_sa[s1 * 16 + hd] + da_l;
            float l2 = d_sa[s2 * 16 + hd] + da_l;
            float l3 = d_sa[s3 * 16 + hd] + da_l;
            uint4 hv0 = *(const uint4*)(d_h1h + (size_t)s0 * 256 + lane * 8);
            uint4 hv1 = *(const uint4*)(d_h1h + (size_t)s1 * 256 + lane * 8);
            uint4 hv2 = *(const uint4*)(d_h1h + (size_t)s2 * 256 + lane * 8);
            uint4 hv3 = *(const uint4*)(d_h1h + (size_t)s3 * 256 + lane * 8);
            l0 = l0 > 0.f ? l0 : 0.2f * l0;
            l1 = l1 > 0.f ? l1 : 0.2f * l1;
            l2 = l2 > 0.f ? l2 : 0.2f * l2;
            l3 = l3 > 0.f ? l3 : 0.2f * l3;
            float nm = fmaxf(fmaxf(m, fmaxf(l0, l1)), fmaxf(l2, l3));
            float sc = __expf(m - nm);
            float e0 = __expf(l0 - nm), e1 = __expf(l1 - nm);
            float e2 = __expf(l2 - nm), e3 = __expf(l3 - nm);
            m = nm;
            z = z * sc + (e0 + e1) + (e2 + e3);
            float2 f0 = __half22float2(*(__half2*)&hv0.x), f1 = __half22float2(*(__half2*)&hv0.y);
            float2 f2 = __half22float2(*(__half2*)&hv0.z), f3 = __half22float2(*(__half2*)&hv0.w);
            float2 g0 = __half22float2(*(__half2*)&hv1.x), g1 = __half22float2(*(__half2*)&hv1.y);
            float2 g2 = __half22float2(*(__half2*)&hv1.z), g3 = __half22float2(*(__half2*)&hv1.w);
            float2 p0 = __half22float2(*(__half2*)&hv2.x), p1 = __half22float2(*(__half2*)&hv2.y);
            float2 p2 = __half22float2(*(__half2*)&hv2.z), p3 = __half22float2(*(__half2*)&hv2.w);
            float2 q0 = __half22float2(*(__half2*)&hv3.x), q1 = __half22float2(*(__half2*)&hv3.y);
            float2 q2 = __half22float2(*(__half2*)&hv3.z), q3 = __half22float2(*(__half2*)&hv3.w);
            acc[0] = acc[0] * sc + (e0 * f0.x + e1 * g0.x) + (e2 * p0.x + e3 * q0.x);
            acc[1] = acc[1] * sc + (e0 * f0.y + e1 * g0.y) + (e2 * p0.y + e3 * q0.y);
            acc[2] = acc[2] * sc + (e0 * f1.x + e1 * g1.x) + (e2 * p1.x + e3 * q1.x);
            acc[3] = acc[3] * sc + (e0 * f1.y + e1 * g1.y) + (e2 * p1.y + e3 * q1.y);
            acc[4] = acc[4] * sc + (e0 * f2.x + e1 * g2.x) + (e2 * p2.x + e3 * q2.x);
            acc[5] = acc[5] * sc + (e0 * f2.y + e1 * g2.y) + (e2 * p2.y + e3 * q2.y);
            acc[6] = acc[6] * sc + (e0 * f3.x + e1 * g3.x) + (e2 * p3.x + e3 * q3.x);
            acc[7] = acc[7] * sc + (e0 * f3.y + e1 * g3.y) + (e2 * p3.y + e3 * q3.y);
            e = en;
            if (!more) break;
            s0 = t0; s1 = t1; s2 = t2; s3 = t3;
        }
    }
    for (; e < end; e++) {
        int s0 = d_csr[e];
        float l0 = d_sa[s0 * 16 + hd] + da_l;
        uint4 hv0 = *(const uint4*)(d_h1h + (size_t)s0 * 256 + lane * 8);
        l0 = l0 > 0.f ? l0 : 0.2f * l0;
        float nm = fmaxf(m, l0);
        float sc = __expf(m - nm);
        float e0 = __expf(l0 - nm);
        m = nm;
        z = z * sc + e0;
        float2 f0 = __half22float2(*(__half2*)&hv0.x), f1 = __half22float2(*(__half2*)&hv0.y);
        float2 f2 = __half22float2(*(__half2*)&hv0.z), f3 = __half22float2(*(__half2*)&hv0.w);
        acc[0] = acc[0] * sc + e0 * f0.x;
        acc[1] = acc[1] * sc + e0 * f0.y;
        acc[2] = acc[2] * sc + e0 * f1.x;
        acc[3] = acc[3] * sc + e0 * f1.y;
        acc[4] = acc[4] * sc + e0 * f2.x;
        acc[5] = acc[5] * sc + e0 * f2.y;
        acc[6] = acc[6] * sc + e0 * f3.x;
        acc[7] = acc[7] * sc + e0 * f3.y;
    }

    float invz = 1.f / (z + 1e-16f);
    float vo[8];
#pragma unroll
    for (int i = 0; i < 8; i++) {
        float v = acc[i] * invz + b[lane * 8 + i];
        vo[i] = v > 0.f ? v : (__expf(v) - 1.f);
    }
    if (SPLIT) {
        __half2 h0 = __floats2half2_rn(vo[0], vo[1]);
        __half2 h1 = __floats2half2_rn(vo[2], vo[3]);
        __half2 h2 = __floats2half2_rn(vo[4], vo[5]);
        __half2 h3 = __floats2half2_rn(vo[6], vo[7]);
        uint4 pk;
        pk.x = *(unsigned*)&h0; pk.y = *(unsigned*)&h1;
        pk.z = *(unsigned*)&h2; pk.w = *(unsigned*)&h3;
        *(uint4*)&d_Ah[(size_t)n * 256 + lane * 8] = pk;
    } else {
        *(float4*)&outf[(size_t)n * 256 + lane * 8] = make_float4(vo[0], vo[1], vo[2], vo[3]);
        *(float4*)&outf[(size_t)n * 256 + lane * 8 + 4] = make_float4(vo[4], vo[5], vo[6], vo[7]);
    }
}

// layer-1 agg (all nodes) | compact tail blocks
#define AB_AGG ((NN * 32) / 256)
#define AB_CMP ((NN + 255) / 256)

__global__ void k_agg1(const float* __restrict__ b) {
    int bid = blockIdx.x;
    if (bid < AB_AGG) {
        int n = (bid * 256 + threadIdx.x) >> 5;
        if (n >= NN) return;
        gat_body<true>(n, threadIdx.x & 31, b, nullptr);
    } else {
        int i = (bid - AB_AGG) * 256 + threadIdx.x;
        if (i < NN && d_mark[i]) {
            int pos = atomicAdd(&d_listcnt, 1);
            d_list[pos] = i;
            d_mark[i] = 0;
        }
    }
}

// layer-2 agg: only listed nodes
__global__ void k_agg2_idx(const float* __restrict__ b) {
    int i = (blockIdx.x * blockDim.x + threadIdx.x) >> 5;
    if (i >= d_listcnt) return;
    gat_body<true>(d_list[i], threadIdx.x & 31, b, nullptr);
}

// layer-3: aggregate ONLY the user/item nodes
__global__ void k_gat_agg_list(const float* __restrict__ b, float* __restrict__ outf,
                               const int* __restrict__ ui, const int* __restrict__ ii,
                               int P) {
    int i = (blockIdx.x * blockDim.x + threadIdx.x) >> 5;
    if (i >= 2 * P) return;
    int n = (i < P) ? ui[i] : ii[i - P];
    gat_body<false>(n, threadIdx.x & 31, b, outf);
}

// ---------------- final ----------------
__global__ void k_final(const float* __restrict__ h, const int* __restrict__ ui,
                        const int* __restrict__ ii, const float* __restrict__ Wd,
                        float* __restrict__ out) {
    int p = (blockIdx.x * blockDim.x + threadIdx.x) >> 5;
    if (p >= 1024) return;
    int lane = threadIdx.x & 31;
    int u = ui[p], it = ii[p];
    float a0 = 0.f, a1 = 0.f;
    for (int k = lane; k < 256; k += 32) {
        float v = h[u * 256 + k];
        a0 += v * Wd[k * 2 + 0];
        a1 += v * Wd[k * 2 + 1];
        float w = h[it * 256 + k];
        a0 += w * Wd[(256 + k) * 2 + 0];
        a1 += w * Wd[(256 + k) * 2 + 1];
    }
#pragma unroll
    for (int off = 16; off >= 1; off >>= 1) {
        a0 += __shfl_down_sync(0xffffffffu, a0, off);
        a1 += __shfl_down_sync(0xffffffffu, a1, off);
    }
    if (lane == 0) {
        float mx = fmaxf(a0, a1);
        float lse = mx + __logf(__expf(a0 - mx) + __expf(a1 - mx));
        out[p * 2 + 0] = a0 - lse;
        out[p * 2 + 1] = a1 - lse;
    }
}

// ---------------- launcher ----------------
extern "C" void kernel_launch(void* const* d_in, const int* in_sizes, int n_in,
                              void* d_out, int out_size) {
    const float* x    = (const float*)d_in[0];
    const int*   ei   = (const int*)d_in[1];
    const float* Hd   = (const float*)d_in[2];
    const int*   ui   = (const int*)d_in[3];
    const int*   ii   = (const int*)d_in[4];
    const float* Wg   = (const float*)d_in[5];
    const float* bg   = (const float*)d_in[6];
    const float* W1   = (const float*)d_in[7];
    const float* a1s  = (const float*)d_in[8];
    const float* a1d  = (const float*)d_in[9];
    const float* b1   = (const float*)d_in[10];
    const float* W2   = (const float*)d_in[11];
    const float* a2s  = (const float*)d_in[12];
    const float* a2d  = (const float*)d_in[13];
    const float* b2   = (const float*)d_in[14];
    const float* W3   = (const float*)d_in[15];
    const float* a3s  = (const float*)d_in[16];
    const float* a3d  = (const float*)d_in[17];
    const float* b3   = (const float*)d_in[18];
    const float* wd   = (const float*)d_in[19];
    const float* wr   = (const float*)d_in[20];
    const float* wdnn = (const float*)d_in[21];
    float* out = (float*)d_out;

    int P = in_sizes[3];   // number of user/item pairs

    void *p_h0, *p_bufA, *p_w2h, *p_w3h;
    cudaGetSymbolAddress(&p_h0, d_h0);
    cudaGetSymbolAddress(&p_bufA, d_bufA);
    cudaGetSymbolAddress(&p_w2h, d_W2h);
    cudaGetSymbolAddress(&p_w3h, d_W3h);
    float* h0   = (float*)p_h0;
    float* bufA = (float*)p_bufA;

    cudaFuncSetAttribute(k_transform_mma,
                         cudaFuncAttributeMaxDynamicSharedMemorySize, SMEM_MMA);
    cudaFuncSetAttribute(k_transform_mma_idx,
                         cudaFuncAttributeMaxDynamicSharedMemorySize, SMEM_MMA);

    // fork: chain B (dense prep) on sB, chain A (graph build) on the default stream
    cudaStream_t sB;
    cudaStreamCreateWithFlags(&sB, cudaStreamNonBlocking);
    cudaEvent_t evFork, evJoin;
    cudaEventCreateWithFlags(&evFork, cudaEventDisableTiming);
    cudaEventCreateWithFlags(&evJoin, cudaEventDisableTiming);

    cudaEventRecord(evFork, 0);
    cudaStreamWaitEvent(sB, evFork, 0);

    // chain B: prepW | gemmA -> gemmB -> xw_dual
    k_prep<<<QB_TOTAL, 256, 0, sB>>>(W2, W3, Hd, wr);
    k_gemmB<<<64, 1024, 0, sB>>>(wd);
    k_xw_dual<<<NN / 16, 256, 0, sB>>>(x, Wg);
    cudaEventRecord(evJoin, sB);

    // chain A: count -> scan -> scatter
    k_count<<<(EE / 8 + 255) / 256, 256>>>(ei + EE);
    k_scan<<<1, 1024>>>();
    k_scatter<<<(ET + 255) / 256, 256>>>(ei);

    // join
    cudaStreamWaitEvent(0, evJoin, 0);

    k_gcn_agg<<<GB_GCN + (2 * P + 255) / 256, 256>>>(bg, ui, ii, P);

    // GAT layer 1 (all nodes) + compact tail
    k_transform16<<<NN / 16, 128>>>(h0, W1, a1s, a1d);
    k_agg1<<<AB_AGG + AB_CMP, 256>>>(b1);

    // GAT layer 2: transform all nodes (A staged once per block, 2 B slices)
    k_transform_mma<<<dim3(NP / 128, 2), 256, SMEM_MMA>>>(
        (const __half*)p_w2h, a2s, a2d);
    k_agg2_idx<<<AB_AGG, 256>>>(b2);

    // GAT layer 3: transform only marked set (indexed), aggregate only listed nodes
    k_transform_mma_idx<<<dim3(NP / 128, 2), 256, SMEM_MMA>>>(
        (const __half*)p_w3h, a3s, a3d);
    k_gat_agg_list<<<(2 * P * 32 + 255) / 256, 256>>>(b3, bufA, ui, ii, P);

    k_final<<<(1024 * 32 + 255) / 256, 256>>>(bufA, ui, ii, wdnn, out);

    cudaEventDestroy(evFork);
    cudaEventDestroy(evJoin);
    cudaStreamDestroy(sB);
}